// round 12
// baseline (speedup 1.0000x reference)
#include <cuda_runtime.h>
#include <cuda_bf16.h>
#include <stdint.h>
#include <math.h>

// Problem constants
#define BB 8
#define CC 1024
#define LL 32
#define NN 8192          // B*C
#define DD 128
#define HH 4
#define HO 512           // H*D
#define RR 3
#define AA 64
#define ENBR 262144      // N*L
#define EPS 1e-5f
#define SCALE 0.08838834764831845f   // 1/sqrt(128)

// ---------------- static device scratch ----------------
__device__ __align__(128) float g_x[NN * DD];
__device__ __align__(128) float g_q[NN * HO];
__device__ __align__(128) __nv_bfloat16 g_kb[NN * HO];
__device__ __align__(128) __nv_bfloat16 g_vb[NN * HO];
__device__ __align__(128) float g_t[NN * HO];      // agg (tf32-rounded)
__device__ __align__(128) float g_y1[NN * DD];
__device__ __align__(128) float g_y2[NN * DD];
__device__ __align__(128) float g_M[RR][2 * HO];
__device__ __align__(128) float g_wsw[RR][DD * DD];
__device__ __align__(128) float g_wqc[RR * DD * HO];
__device__ __align__(128) float g_wkc[RR * DD * HO];
__device__ __align__(128) float g_wvc[RR * DD * HO];
__device__ __align__(128) float g_woc[RR * HO * DD];
__device__ __align__(128) float g_wac[DD * AA];
__device__ int   g_indptr[NN + 1];
__device__ int   g_cnt[NN];
__device__ int   g_cursor[NN];
__device__ int   g_esrc[ENBR];
__device__ __align__(16) float2 g_erel[ENBR];
__device__ int   g_fmt[1];

__device__ __forceinline__ unsigned f2tf32(float x) {
    unsigned r;
    asm("cvt.rna.tf32.f32 %0, %1;" : "=r"(r) : "f"(x));
    return r;
}
__device__ __forceinline__ float tf32r(float x) { return __uint_as_float(f2tf32(x)); }

// ---------------- setup kernels ----------------
// fused: tf32 copies of weights AND x0
__global__ void conv_kernel(const float* __restrict__ Wq, const float* __restrict__ Wk,
                            const float* __restrict__ Wv, const float* __restrict__ Wout,
                            const float* __restrict__ Wact, const float* __restrict__ nf) {
    int i = blockIdx.x * blockDim.x + threadIdx.x;
    const int S = RR * DD * HO;
    if (i < S) {
        g_wqc[i] = tf32r(Wq[i]);
        g_wkc[i] = tf32r(Wk[i]);
        g_wvc[i] = tf32r(Wv[i]);
        g_woc[i] = tf32r(Wout[i]);
        if (i < DD * AA) g_wac[i] = tf32r(Wact[i]);
    }
    if (i < NN * DD) g_x[i] = tf32r(nf[i]);
}

__global__ void zero_detect_kernel(const int* __restrict__ ids) {
    int i = blockIdx.x * blockDim.x + threadIdx.x;
    if (i < NN) g_cnt[i] = 0;
    if (blockIdx.x == 0 && threadIdx.x < 32) {
        int nz = 0;
        for (int k2 = threadIdx.x; k2 < 64; k2 += 32)
            nz |= (ids[2 * k2 + 1] != 0);
        nz = __any_sync(0xffffffffu, nz);
        if (threadIdx.x == 0) g_fmt[0] = nz ? 0 : 1;
    }
}

__device__ __forceinline__ int load_id(const int* __restrict__ ids, int idx, int fmt64) {
    return fmt64 ? ids[2 * idx] : ids[idx];
}

__global__ void count_kernel(const int* __restrict__ ids) {
    int idx = blockIdx.x * blockDim.x + threadIdx.x;
    if (idx >= ENBR) return;
    int fmt = g_fmt[0];
    int id = load_id(ids, idx, fmt);
    int n = idx >> 5;
    int dst = (n & ~(CC - 1)) | id;
    atomicAdd(&g_cnt[dst], 1);
}

// warp-shuffle scan (1024 threads, 8 elems each)
__global__ void scan_kernel() {
    __shared__ int wsum[32];
    int t = threadIdx.x;
    int lane = t & 31, wid = t >> 5;
    int local[8];
    int s = 0;
#pragma unroll
    for (int i = 0; i < 8; i++) { local[i] = g_cnt[t * 8 + i]; s += local[i]; }
    int v = s;
#pragma unroll
    for (int off = 1; off < 32; off <<= 1) {
        int u = __shfl_up_sync(0xffffffffu, v, off);
        if (lane >= off) v += u;
    }
    if (lane == 31) wsum[wid] = v;
    __syncthreads();
    if (wid == 0) {
        int wv = wsum[lane];
#pragma unroll
        for (int off = 1; off < 32; off <<= 1) {
            int u = __shfl_up_sync(0xffffffffu, wv, off);
            if (lane >= off) wv += u;
        }
        wsum[lane] = wv;
    }
    __syncthreads();
    int base = (wid ? wsum[wid - 1] : 0) + v - s;   // exclusive prefix for this thread
#pragma unroll
    for (int i = 0; i < 8; i++) {
        g_indptr[t * 8 + i] = base;
        g_cursor[t * 8 + i] = base;
        base += local[i];
    }
    if (t == 1023) g_indptr[NN] = base;
}

__global__ void scatter_kernel(const int* __restrict__ ids, const float* __restrict__ rc) {
    int idx = blockIdx.x * blockDim.x + threadIdx.x;
    if (idx >= ENBR) return;
    int fmt = g_fmt[0];
    int id = load_id(ids, idx, fmt);
    int n = idx >> 5;
    int l = idx & 31;
    int dst = (n & ~(CC - 1)) | id;
    int pos = atomicAdd(&g_cursor[dst], 1);
    g_esrc[pos] = n;
    g_erel[pos] = make_float2(rc[n * (2 * LL) + 2 * l], rc[n * (2 * LL) + 2 * l + 1]);
}

__global__ __launch_bounds__(128) void prep_kernel(
    const float* __restrict__ We, const float* __restrict__ Wedge,
    const float* __restrict__ Wskip, const float* __restrict__ Wout)
{
    int r = blockIdx.y;
    const float* Wer = We + (size_t)r * 2 * DD;
    const float* Wedger = Wedge + (size_t)r * DD * HO;
    const float* Wskipr = Wskip + (size_t)r * DD * HO;
    const float* Woutr = Wout + (size_t)r * HO * DD;
    int b = blockIdx.x;
    if (b < DD) {
        __shared__ float row[HO];
        for (int i = threadIdx.x; i < HO; i += 128) row[i] = Wskipr[b * HO + i];
        __syncthreads();
        float s = 0.f;
        for (int k2 = 0; k2 < HO; k2++) s += row[k2] * Woutr[k2 * DD + threadIdx.x];
        g_wsw[r][b * DD + threadIdx.x] = tf32r(s);
    } else {
        int o = (b - DD) * 128 + threadIdx.x;
        float s0 = 0.f, s1 = 0.f;
        for (int d = 0; d < DD; d++) {
            float w = Wedger[d * HO + o];
            s0 += Wer[d] * w;
            s1 += Wer[DD + d] * w;
        }
        g_M[r][o] = s0;
        g_M[r][HO + o] = s1;
    }
}

// ---------------- tf32 GEMM core (cp.async + ldmatrix) ----------------
__device__ __forceinline__ void mma_tf32(float* c, unsigned a0, unsigned a1, unsigned a2,
                                         unsigned a3, unsigned b0, unsigned b1) {
    asm volatile(
        "mma.sync.aligned.m16n8k8.row.col.f32.tf32.tf32.f32 "
        "{%0,%1,%2,%3}, {%4,%5,%6,%7}, {%8,%9}, {%0,%1,%2,%3};"
        : "+f"(c[0]), "+f"(c[1]), "+f"(c[2]), "+f"(c[3])
        : "r"(a0), "r"(a1), "r"(a2), "r"(a3), "r"(b0), "r"(b1));
}

__device__ __forceinline__ void ldm4(unsigned* r, unsigned addr) {
    asm volatile("ldmatrix.sync.aligned.m8n8.x4.shared.b16 {%0,%1,%2,%3}, [%4];"
                 : "=r"(r[0]), "=r"(r[1]), "=r"(r[2]), "=r"(r[3]) : "r"(addr));
}

__device__ __forceinline__ void gemm_phase(
    const float* __restrict__ Ap, const float* __restrict__ Bp, int kd, int Ndim,
    unsigned sbase, int tid, int bm, int bn,
    unsigned a_l, unsigned b_l, float acc[2][4][4])
{
    const int arow = tid >> 2, akq = tid & 3;
    const float* asrc = Ap + (size_t)(bm + arow) * kd + akq * 4;
    const size_t asrc2 = (size_t)64 * kd;
    const unsigned adst = sbase + arow * 80 + akq * 16;

    const int bnn = tid & 63, bk4 = (tid >> 6) * 4;
    const float* bsrc = Bp + (size_t)bk4 * Ndim + bn + bnn;
    const unsigned bdst = sbase + 30720 + bnn * 80 + bk4 * 4;
    float br0, br1, br2, br3;
    const int nch = kd >> 4;

#define CPA(c, bufA) do {                                                        \
    const float* s0_ = asrc + (c) * 16;                                          \
    unsigned d0_ = adst + (bufA) * 10240;                                        \
    asm volatile("cp.async.cg.shared.global [%0],[%1],16;\n"                     \
                 "cp.async.cg.shared.global [%2],[%3],16;\n"                     \
                 "cp.async.commit_group;\n"                                      \
                 :: "r"(d0_), "l"(s0_), "r"(d0_ + 64 * 80), "l"(s0_ + asrc2));   \
} while (0)
#define LDGB(c) do {                                                             \
    const float* p_ = bsrc + (size_t)(c) * 16 * Ndim;                            \
    br0 = __ldg(p_); br1 = __ldg(p_ + Ndim);                                     \
    br2 = __ldg(p_ + 2 * (size_t)Ndim); br3 = __ldg(p_ + 3 * (size_t)Ndim);      \
} while (0)
#define STSB(bufB)                                                               \
    asm volatile("st.shared.v4.f32 [%0], {%1,%2,%3,%4};"                         \
                 :: "r"(bdst + (bufB) * 5120), "f"(br0), "f"(br1), "f"(br2), "f"(br3))

    CPA(0, 0);
    CPA(1, 1);
    LDGB(0);
    STSB(0);
    LDGB(1);
    asm volatile("cp.async.wait_group 1;" ::: "memory");
    __syncthreads();

    int bufA = 0;
    for (int c = 0; c < nch; c++) {
        int bufB = c & 1;
        if (c + 2 < nch) {
            int tb = bufA + 2; if (tb >= 3) tb -= 3;
            CPA(c + 2, tb);
        }
        const unsigned abase = a_l + bufA * 10240;
        const unsigned bbase = b_l + bufB * 5120;
#pragma unroll
        for (int kk = 0; kk < 2; kk++) {
            unsigned a[2][4], b[2][4];
            ldm4(a[0], abase + kk * 32);
            ldm4(a[1], abase + 1280 + kk * 32);
            ldm4(b[0], bbase + kk * 32);
            ldm4(b[1], bbase + 1280 + kk * 32);
#pragma unroll
            for (int i = 0; i < 2; i++) {
                mma_tf32(acc[i][0], a[i][0], a[i][1], a[i][2], a[i][3], b[0][0], b[0][1]);
                mma_tf32(acc[i][1], a[i][0], a[i][1], a[i][2], a[i][3], b[0][2], b[0][3]);
                mma_tf32(acc[i][2], a[i][0], a[i][1], a[i][2], a[i][3], b[1][0], b[1][1]);
                mma_tf32(acc[i][3], a[i][0], a[i][1], a[i][2], a[i][3], b[1][2], b[1][3]);
            }
        }
        if (c < nch - 1) {
            STSB(bufB ^ 1);
            if (c + 2 < nch) {
                LDGB(c + 2);
                asm volatile("cp.async.wait_group 1;" ::: "memory");
            } else {
                asm volatile("cp.async.wait_group 0;" ::: "memory");
            }
            __syncthreads();
        }
        if (++bufA == 3) bufA = 0;
    }
#undef CPA
#undef LDGB
#undef STSB
}

// z-sliced GEMM with per-slice A, B, C, K
__global__ __launch_bounds__(256) void tf32gemm_kernel(
    const float* __restrict__ A0, const float* __restrict__ A1,
    const float* __restrict__ A2,
    const float* __restrict__ B0, const float* __restrict__ B1,
    const float* __restrict__ B2,
    void* __restrict__ C0, void* __restrict__ C1, void* __restrict__ C2,
    int bfmask, int Ndim, int4 Kdims)
{
    const float* Ap;
    const float* Bp;
    void* Cp;
    int kd;
    switch (blockIdx.z) {
        case 0: Ap = A0; Bp = B0; Cp = C0; kd = Kdims.x; break;
        case 1: Ap = A1; Bp = B1; Cp = C1; kd = Kdims.y; break;
        default: Ap = A2; Bp = B2; Cp = C2; kd = Kdims.z; break;
    }
    const bool bf16out = (bfmask >> blockIdx.z) & 1;

    __shared__ __align__(16) char smem_raw[40960];
    const unsigned sbase = (unsigned)__cvta_generic_to_shared(smem_raw);

    const int tid = threadIdx.x;
    const int bm = blockIdx.y * 128, bn = blockIdx.x * 64;
    const int lane = tid & 31;
    const int w = tid >> 5;
    const int wm = w & 3, wn = w >> 2;
    const int lq = lane >> 2, lr = lane & 3;

    const unsigned a_l = sbase + (wm * 32 + (lane & 15)) * 80 + (lane >> 4) * 16;
    const unsigned b_l = sbase + 30720 +
        (wn * 32 + (lane & 7) + ((lane >> 4) & 1) * 8) * 80 + ((lane >> 3) & 1) * 16;

    float acc[2][4][4];
#pragma unroll
    for (int i = 0; i < 2; i++)
#pragma unroll
        for (int j = 0; j < 4; j++)
#pragma unroll
            for (int u = 0; u < 4; u++) acc[i][j][u] = 0.f;

    gemm_phase(Ap, Bp, kd, Ndim, sbase, tid, bm, bn, a_l, b_l, acc);

#pragma unroll
    for (int i = 0; i < 2; i++) {
#pragma unroll
        for (int j = 0; j < 4; j++) {
            int row = bm + wm * 32 + i * 16 + lq;
            int col = bn + wn * 32 + j * 8 + lr * 2;
            if (bf16out) {
                __nv_bfloat16* Cb = (__nv_bfloat16*)Cp;
                *(__nv_bfloat162*)(Cb + (size_t)row * Ndim + col) =
                    __float22bfloat162_rn(make_float2(acc[i][j][0], acc[i][j][1]));
                *(__nv_bfloat162*)(Cb + (size_t)(row + 8) * Ndim + col) =
                    __float22bfloat162_rn(make_float2(acc[i][j][2], acc[i][j][3]));
            } else {
                float* Cf = (float*)Cp;
                *(float2*)(Cf + (size_t)row * Ndim + col) =
                    make_float2(acc[i][j][0], acc[i][j][1]);
                *(float2*)(Cf + (size_t)(row + 8) * Ndim + col) =
                    make_float2(acc[i][j][2], acc[i][j][3]);
            }
        }
    }
}

// ---------------- attention (rank-2 edge algebra + ILP-4 + prefetch) ----------------
__device__ __forceinline__ float2 bf2f(unsigned u) {
    __nv_bfloat162 h = *reinterpret_cast<__nv_bfloat162*>(&u);
    return __bfloat1622float2(h);
}

__global__ __launch_bounds__(128) void attn_kernel(int r) {
    int j = blockIdx.x;
    int warp = threadIdx.x >> 5;
    int lane = threadIdx.x & 31;
    const int hd0 = warp * DD + lane * 4;
    const size_t jbase = (size_t)j * HO + hd0;

    float4 qv = *(const float4*)(g_q + jbase);
    float qr[4] = {qv.x, qv.y, qv.z, qv.w};
    float Mx[4], My[4];
#pragma unroll
    for (int u = 0; u < 4; u++) { Mx[u] = g_M[r][hd0 + u]; My[u] = g_M[r][HO + hd0 + u]; }
    const float qMx = qr[0] * Mx[0] + qr[1] * Mx[1] + qr[2] * Mx[2] + qr[3] * Mx[3];
    const float qMy = qr[0] * My[0] + qr[1] * My[1] + qr[2] * My[2] + qr[3] * My[3];

    float m, den = 1.f, acc[4];
    float cx = 0.f, cy = 0.f;
    {
        uint2 kr = *(const uint2*)(g_kb + jbase);
        uint2 vr = *(const uint2*)(g_vb + jbase);
        float2 k01 = bf2f(kr.x), k23 = bf2f(kr.y);
        float2 v01 = bf2f(vr.x), v23 = bf2f(vr.y);
        float part = qr[0] * k01.x + qr[1] * k01.y + qr[2] * k23.x + qr[3] * k23.y;
#pragma unroll
        for (int o = 16; o; o >>= 1) part += __shfl_xor_sync(0xffffffffu, part, o);
        m = part * SCALE;
        acc[0] = v01.x; acc[1] = v01.y; acc[2] = v23.x; acc[3] = v23.y;
    }

    const int e0 = g_indptr[j], e1 = g_indptr[j + 1];
    const int nbat = (e1 - e0) >> 2;

    float2 rrC[4];
    uint2 krC[4], vrC[4];
    if (nbat > 0) {
#pragma unroll
        for (int i = 0; i < 4; i++) {
            int s = __ldg(g_esrc + e0 + i);
            rrC[i] = __ldg(g_erel + e0 + i);
            krC[i] = *(const uint2*)(g_kb + (size_t)s * HO + hd0);
            vrC[i] = *(const uint2*)(g_vb + (size_t)s * HO + hd0);
        }
    }
    for (int b = 0; b < nbat; b++) {
        float2 rrN[4];
        uint2 krN[4], vrN[4];
        const bool more = (b + 1 < nbat);
        if (more) {
            int base = e0 + (b + 1) * 4;
#pragma unroll
            for (int i = 0; i < 4; i++) {
                int s = __ldg(g_esrc + base + i);
                rrN[i] = __ldg(g_erel + base + i);
                krN[i] = *(const uint2*)(g_kb + (size_t)s * HO + hd0);
                vrN[i] = *(const uint2*)(g_vb + (size_t)s * HO + hd0);
            }
        }
        // compute on current batch
        float part[4];
#pragma unroll
        for (int i = 0; i < 4; i++) {
            float2 k01 = bf2f(krC[i].x), k23 = bf2f(krC[i].y);
            part[i] = qr[0] * k01.x + qr[1] * k01.y + qr[2] * k23.x + qr[3] * k23.y
                    + rrC[i].x * qMx + rrC[i].y * qMy;
        }
#pragma unroll
        for (int o = 16; o; o >>= 1) {
#pragma unroll
            for (int i = 0; i < 4; i++)
                part[i] += __shfl_xor_sync(0xffffffffu, part[i], o);
        }
        float a0 = part[0] * SCALE, a1 = part[1] * SCALE;
        float a2 = part[2] * SCALE, a3 = part[3] * SCALE;
        float mb = fmaxf(fmaxf(a0, a1), fmaxf(a2, a3));
        float mn = fmaxf(m, mb);
        float fold = __expf(m - mn);
        float w0 = __expf(a0 - mn), w1 = __expf(a1 - mn);
        float w2 = __expf(a2 - mn), w3 = __expf(a3 - mn);
        den = den * fold + (w0 + w1 + w2 + w3);
        cx = cx * fold + (w0 * rrC[0].x + w1 * rrC[1].x + w2 * rrC[2].x + w3 * rrC[3].x);
        cy = cy * fold + (w0 * rrC[0].y + w1 * rrC[1].y + w2 * rrC[2].y + w3 * rrC[3].y);
        float2 v01[4], v23[4];
#pragma unroll
        for (int i = 0; i < 4; i++) { v01[i] = bf2f(vrC[i].x); v23[i] = bf2f(vrC[i].y); }
        acc[0] = acc[0] * fold + (w0 * v01[0].x + w1 * v01[1].x + w2 * v01[2].x + w3 * v01[3].x);
        acc[1] = acc[1] * fold + (w0 * v01[0].y + w1 * v01[1].y + w2 * v01[2].y + w3 * v01[3].y);
        acc[2] = acc[2] * fold + (w0 * v23[0].x + w1 * v23[1].x + w2 * v23[2].x + w3 * v23[3].x);
        acc[3] = acc[3] * fold + (w0 * v23[0].y + w1 * v23[1].y + w2 * v23[2].y + w3 * v23[3].y);
        m = mn;
        if (more) {
#pragma unroll
            for (int i = 0; i < 4; i++) { rrC[i] = rrN[i]; krC[i] = krN[i]; vrC[i] = vrN[i]; }
        }
    }
    // tail
    for (int ei = e0 + nbat * 4; ei < e1; ++ei) {
        int s = __ldg(g_esrc + ei);
        float2 rr = __ldg(g_erel + ei);
        uint2 kr = *(const uint2*)(g_kb + (size_t)s * HO + hd0);
        uint2 vr = *(const uint2*)(g_vb + (size_t)s * HO + hd0);
        float2 k01 = bf2f(kr.x), k23 = bf2f(kr.y);
        float part = qr[0] * k01.x + qr[1] * k01.y + qr[2] * k23.x + qr[3] * k23.y
                   + rr.x * qMx + rr.y * qMy;
#pragma unroll
        for (int o = 16; o; o >>= 1) part += __shfl_xor_sync(0xffffffffu, part, o);
        float alpha = part * SCALE;
        float mn = fmaxf(m, alpha);
        float fold = __expf(m - mn);
        float wgt = __expf(alpha - mn);
        den = den * fold + wgt;
        cx = cx * fold + wgt * rr.x;
        cy = cy * fold + wgt * rr.y;
        float2 v01 = bf2f(vr.x), v23 = bf2f(vr.y);
        acc[0] = acc[0] * fold + wgt * v01.x;
        acc[1] = acc[1] * fold + wgt * v01.y;
        acc[2] = acc[2] * fold + wgt * v23.x;
        acc[3] = acc[3] * fold + wgt * v23.y;
        m = mn;
    }

    float inv = 1.f / den;
#pragma unroll
    for (int u = 0; u < 4; u++)
        acc[u] = (acc[u] + cx * Mx[u] + cy * My[u]) * inv;
    *(float4*)(g_t + jbase) = make_float4(tf32r(acc[0]), tf32r(acc[1]),
                                          tf32r(acc[2]), tf32r(acc[3]));
}

// x_out = tf32(rmsnorm(y1 + y2 + x_in, ln_w))
__global__ __launch_bounds__(128) void rmsres_kernel(const float* __restrict__ lnw) {
    int j = blockIdx.x, d = threadIdx.x;
    size_t i = (size_t)j * DD + d;
    float val = g_y1[i] + g_y2[i] + g_x[i];
    float ss = val * val;
#pragma unroll
    for (int off = 16; off; off >>= 1) ss += __shfl_xor_sync(0xffffffffu, ss, off);
    __shared__ float w4[4];
    if ((threadIdx.x & 31) == 0) w4[threadIdx.x >> 5] = ss;
    __syncthreads();
    float tot = w4[0] + w4[1] + w4[2] + w4[3];
    float r = rsqrtf(tot / (float)DD + EPS);
    g_x[i] = tf32r(val * r * lnw[d]);
}

// out = rmsnorm(y, ln_f)
__global__ __launch_bounds__(64) void rmsfinal_kernel(const float* __restrict__ y,
                                                      const float* __restrict__ lnf,
                                                      float* __restrict__ out) {
    int j = blockIdx.x, d = threadIdx.x;
    float val = y[(size_t)j * AA + d];
    float ss = val * val;
#pragma unroll
    for (int off = 16; off; off >>= 1) ss += __shfl_xor_sync(0xffffffffu, ss, off);
    __shared__ float w2[2];
    if ((threadIdx.x & 31) == 0) w2[threadIdx.x >> 5] = ss;
    __syncthreads();
    float tot = w2[0] + w2[1];
    float r = rsqrtf(tot / (float)AA + EPS);
    out[(size_t)j * AA + d] = val * r * lnf[d];
}

// ---------------- launch ----------------
extern "C" void kernel_launch(void* const* d_in, const int* in_sizes, int n_in,
                              void* d_out, int out_size) {
    const float* node_features = (const float*)d_in[0];
    const int*   ids           = (const int*)d_in[1];
    const float* rel           = (const float*)d_in[2];
    const float* We_emb        = (const float*)d_in[3];
    const float* Wq            = (const float*)d_in[4];
    const float* Wk            = (const float*)d_in[5];
    const float* Wv            = (const float*)d_in[6];
    const float* Wedge         = (const float*)d_in[7];
    const float* Wskip         = (const float*)d_in[8];
    const float* Wout          = (const float*)d_in[9];
    const float* lnw           = (const float*)d_in[10];
    const float* Wact          = (const float*)d_in[11];
    const float* lnf           = (const float*)d_in[12];
    float* out = (float*)d_out;

    float *xp, *qp, *tp, *y1p, *y2p, *wswp, *wqcp, *wkcp, *wvcp, *wocp, *wacp;
    __nv_bfloat16 *kbp, *vbp;
    cudaGetSymbolAddress((void**)&xp, g_x);
    cudaGetSymbolAddress((void**)&qp, g_q);
    cudaGetSymbolAddress((void**)&kbp, g_kb);
    cudaGetSymbolAddress((void**)&vbp, g_vb);
    cudaGetSymbolAddress((void**)&tp, g_t);
    cudaGetSymbolAddress((void**)&y1p, g_y1);
    cudaGetSymbolAddress((void**)&y2p, g_y2);
    cudaGetSymbolAddress((void**)&wswp, g_wsw);
    cudaGetSymbolAddress((void**)&wqcp, g_wqc);
    cudaGetSymbolAddress((void**)&wkcp, g_wkc);
    cudaGetSymbolAddress((void**)&wvcp, g_wvc);
    cudaGetSymbolAddress((void**)&wocp, g_woc);
    cudaGetSymbolAddress((void**)&wacp, g_wac);

    dim3 gqkv(HO / 64, NN / 128, 3);
    dim3 gyy(DD / 64, NN / 128, 2);
    dim3 gf(AA / 64, NN / 128, 1);

    // QKV round 0 at launch index 3 (the ncu-profiled slot)
    conv_kernel<<<(NN * DD + 255) / 256, 256>>>(Wq, Wk, Wv, Wout, Wact, node_features);
    zero_detect_kernel<<<(NN + 255) / 256, 256>>>(ids);
    count_kernel<<<(ENBR + 255) / 256, 256>>>(ids);
    tf32gemm_kernel<<<gqkv, 256>>>(xp, xp, xp, wqcp, wkcp, wvcp,
                                   qp, kbp, vbp, /*bfmask=*/0b110, HO,
                                   make_int4(DD, DD, DD, 0));
    scan_kernel<<<1, 1024>>>();
    scatter_kernel<<<(ENBR + 255) / 256, 256>>>(ids, rel);
    prep_kernel<<<dim3(DD + 4, RR), 128>>>(We_emb, Wedge, Wskip, Wout);

    for (int r = 0; r < RR; r++) {
        if (r > 0) {
            const float* wq = wqcp + (size_t)r * DD * HO;
            const float* wk = wkcp + (size_t)r * DD * HO;
            const float* wv = wvcp + (size_t)r * DD * HO;
            tf32gemm_kernel<<<gqkv, 256>>>(xp, xp, xp, wq, wk, wv,
                                           qp, kbp, vbp, 0b110, HO,
                                           make_int4(DD, DD, DD, 0));
        }
        attn_kernel<<<NN, 128>>>(r);
        // z=0: y1 = agg @ Wout (K=512); z=1: y2 = x @ Wsw (K=128)
        tf32gemm_kernel<<<gyy, 256>>>(tp, xp, xp,
                                      wocp + (size_t)r * HO * DD,
                                      wswp + (size_t)r * DD * DD,
                                      wswp + (size_t)r * DD * DD,
                                      y1p, y2p, y2p, /*bfmask=*/0, DD,
                                      make_int4(HO, DD, DD, 0));
        rmsres_kernel<<<NN, DD>>>(lnw + (size_t)r * DD);
    }

    tf32gemm_kernel<<<gf, 256>>>(xp, xp, xp, wacp, wacp, wacp,
                                 y1p, y1p, y1p, /*bfmask=*/0, AA,
                                 make_int4(DD, DD, DD, 0));
    rmsfinal_kernel<<<NN, AA>>>(y1p, lnf, out);
}

// round 13
// speedup vs baseline: 1.0794x; 1.0794x over previous
#include <cuda_runtime.h>
#include <cuda_bf16.h>
#include <stdint.h>
#include <math.h>

// Problem constants
#define BB 8
#define CC 1024
#define LL 32
#define NN 8192          // B*C
#define DD 128
#define HH 4
#define HO 512           // H*D
#define RR 3
#define AA 64
#define ENBR 262144      // N*L
#define EPS 1e-5f
#define SCALE 0.08838834764831845f   // 1/sqrt(128)

// ---------------- static device scratch ----------------
__device__ __align__(128) float g_x[NN * DD];
__device__ __align__(128) float g_q[NN * HO];
__device__ __align__(128) __nv_bfloat16 g_kb[NN * HO];
__device__ __align__(128) __nv_bfloat16 g_vb[NN * HO];
__device__ __align__(128) float g_t[NN * HO];
__device__ __align__(128) float g_y1[NN * DD];
__device__ __align__(128) float g_M[RR][2 * HO];
__device__ __align__(128) float g_wsw[RR][DD * DD];
__device__ __align__(128) float g_wqc[RR * DD * HO];
__device__ __align__(128) float g_wkc[RR * DD * HO];
__device__ __align__(128) float g_wvc[RR * DD * HO];
__device__ __align__(128) float g_woc[RR * HO * DD];
__device__ __align__(128) float g_wac[DD * AA];
__device__ int   g_indptr[NN + 1];
__device__ int   g_cnt[NN];
__device__ int   g_cursor[NN];
__device__ int   g_esrc[ENBR];
__device__ __align__(16) float2 g_erel[ENBR];
__device__ int   g_fmt[1];

__device__ __forceinline__ unsigned f2tf32(float x) {
    unsigned r;
    asm("cvt.rna.tf32.f32 %0, %1;" : "=r"(r) : "f"(x));
    return r;
}
__device__ __forceinline__ float tf32r(float x) { return __uint_as_float(f2tf32(x)); }

// ---------------- setup kernels ----------------
__global__ void conv_kernel(const float* __restrict__ Wq, const float* __restrict__ Wk,
                            const float* __restrict__ Wv, const float* __restrict__ Wout,
                            const float* __restrict__ Wact, const float* __restrict__ nf) {
    int i = blockIdx.x * blockDim.x + threadIdx.x;
    const int S = RR * DD * HO;
    if (i < S) {
        g_wqc[i] = tf32r(Wq[i]);
        g_wkc[i] = tf32r(Wk[i]);
        g_wvc[i] = tf32r(Wv[i]);
        g_woc[i] = tf32r(Wout[i]);
        if (i < DD * AA) g_wac[i] = tf32r(Wact[i]);
    }
    if (i < NN * DD) g_x[i] = tf32r(nf[i]);
}

__global__ void zero_detect_kernel(const int* __restrict__ ids) {
    int i = blockIdx.x * blockDim.x + threadIdx.x;
    if (i < NN) g_cnt[i] = 0;
    if (blockIdx.x == 0 && threadIdx.x < 32) {
        int nz = 0;
        for (int k2 = threadIdx.x; k2 < 64; k2 += 32)
            nz |= (ids[2 * k2 + 1] != 0);
        nz = __any_sync(0xffffffffu, nz);
        if (threadIdx.x == 0) g_fmt[0] = nz ? 0 : 1;
    }
}

__device__ __forceinline__ int load_id(const int* __restrict__ ids, int idx, int fmt64) {
    return fmt64 ? ids[2 * idx] : ids[idx];
}

__global__ void count_kernel(const int* __restrict__ ids) {
    int idx = blockIdx.x * blockDim.x + threadIdx.x;
    if (idx >= ENBR) return;
    int fmt = g_fmt[0];
    int id = load_id(ids, idx, fmt);
    int n = idx >> 5;
    int dst = (n & ~(CC - 1)) | id;
    atomicAdd(&g_cnt[dst], 1);
}

// warp-shuffle scan (1024 threads, 8 elems each)
__global__ void scan_kernel() {
    __shared__ int wsum[32];
    int t = threadIdx.x;
    int lane = t & 31, wid = t >> 5;
    int local[8];
    int s = 0;
#pragma unroll
    for (int i = 0; i < 8; i++) { local[i] = g_cnt[t * 8 + i]; s += local[i]; }
    int v = s;
#pragma unroll
    for (int off = 1; off < 32; off <<= 1) {
        int u = __shfl_up_sync(0xffffffffu, v, off);
        if (lane >= off) v += u;
    }
    if (lane == 31) wsum[wid] = v;
    __syncthreads();
    if (wid == 0) {
        int wv = wsum[lane];
#pragma unroll
        for (int off = 1; off < 32; off <<= 1) {
            int u = __shfl_up_sync(0xffffffffu, wv, off);
            if (lane >= off) wv += u;
        }
        wsum[lane] = wv;
    }
    __syncthreads();
    int base = (wid ? wsum[wid - 1] : 0) + v - s;
#pragma unroll
    for (int i = 0; i < 8; i++) {
        g_indptr[t * 8 + i] = base;
        g_cursor[t * 8 + i] = base;
        base += local[i];
    }
    if (t == 1023) g_indptr[NN] = base;
}

__global__ void scatter_kernel(const int* __restrict__ ids, const float* __restrict__ rc) {
    int idx = blockIdx.x * blockDim.x + threadIdx.x;
    if (idx >= ENBR) return;
    int fmt = g_fmt[0];
    int id = load_id(ids, idx, fmt);
    int n = idx >> 5;
    int l = idx & 31;
    int dst = (n & ~(CC - 1)) | id;
    int pos = atomicAdd(&g_cursor[dst], 1);
    g_esrc[pos] = n;
    g_erel[pos] = make_float2(rc[n * (2 * LL) + 2 * l], rc[n * (2 * LL) + 2 * l + 1]);
}

__global__ __launch_bounds__(128) void prep_kernel(
    const float* __restrict__ We, const float* __restrict__ Wedge,
    const float* __restrict__ Wskip, const float* __restrict__ Wout)
{
    int r = blockIdx.y;
    const float* Wer = We + (size_t)r * 2 * DD;
    const float* Wedger = Wedge + (size_t)r * DD * HO;
    const float* Wskipr = Wskip + (size_t)r * DD * HO;
    const float* Woutr = Wout + (size_t)r * HO * DD;
    int b = blockIdx.x;
    if (b < DD) {
        __shared__ float row[HO];
        for (int i = threadIdx.x; i < HO; i += 128) row[i] = Wskipr[b * HO + i];
        __syncthreads();
        float s = 0.f;
        for (int k2 = 0; k2 < HO; k2++) s += row[k2] * Woutr[k2 * DD + threadIdx.x];
        g_wsw[r][b * DD + threadIdx.x] = tf32r(s);
    } else {
        int o = (b - DD) * 128 + threadIdx.x;
        float s0 = 0.f, s1 = 0.f;
        for (int d = 0; d < DD; d++) {
            float w = Wedger[d * HO + o];
            s0 += Wer[d] * w;
            s1 += Wer[DD + d] * w;
        }
        g_M[r][o] = s0;
        g_M[r][HO + o] = s1;
    }
}

// ---------------- tf32 GEMM core (cp.async + ldmatrix) ----------------
__device__ __forceinline__ void mma_tf32(float* c, unsigned a0, unsigned a1, unsigned a2,
                                         unsigned a3, unsigned b0, unsigned b1) {
    asm volatile(
        "mma.sync.aligned.m16n8k8.row.col.f32.tf32.tf32.f32 "
        "{%0,%1,%2,%3}, {%4,%5,%6,%7}, {%8,%9}, {%0,%1,%2,%3};"
        : "+f"(c[0]), "+f"(c[1]), "+f"(c[2]), "+f"(c[3])
        : "r"(a0), "r"(a1), "r"(a2), "r"(a3), "r"(b0), "r"(b1));
}

__device__ __forceinline__ void ldm4(unsigned* r, unsigned addr) {
    asm volatile("ldmatrix.sync.aligned.m8n8.x4.shared.b16 {%0,%1,%2,%3}, [%4];"
                 : "=r"(r[0]), "=r"(r[1]), "=r"(r[2]), "=r"(r[3]) : "r"(addr));
}

__device__ __forceinline__ void gemm_phase(
    const float* __restrict__ Ap, const float* __restrict__ Bp, int kd, int Ndim,
    unsigned sbase, int tid, int bm, int bn,
    unsigned a_l, unsigned b_l, float acc[2][4][4])
{
    const int arow = tid >> 2, akq = tid & 3;
    const float* asrc = Ap + (size_t)(bm + arow) * kd + akq * 4;
    const size_t asrc2 = (size_t)64 * kd;
    const unsigned adst = sbase + arow * 80 + akq * 16;

    const int bnn = tid & 63, bk4 = (tid >> 6) * 4;
    const float* bsrc = Bp + (size_t)bk4 * Ndim + bn + bnn;
    const unsigned bdst = sbase + 30720 + bnn * 80 + bk4 * 4;
    float br0, br1, br2, br3;
    const int nch = kd >> 4;

#define CPA(c, bufA) do {                                                        \
    const float* s0_ = asrc + (c) * 16;                                          \
    unsigned d0_ = adst + (bufA) * 10240;                                        \
    asm volatile("cp.async.cg.shared.global [%0],[%1],16;\n"                     \
                 "cp.async.cg.shared.global [%2],[%3],16;\n"                     \
                 "cp.async.commit_group;\n"                                      \
                 :: "r"(d0_), "l"(s0_), "r"(d0_ + 64 * 80), "l"(s0_ + asrc2));   \
} while (0)
#define LDGB(c) do {                                                             \
    const float* p_ = bsrc + (size_t)(c) * 16 * Ndim;                            \
    br0 = __ldg(p_); br1 = __ldg(p_ + Ndim);                                     \
    br2 = __ldg(p_ + 2 * (size_t)Ndim); br3 = __ldg(p_ + 3 * (size_t)Ndim);      \
} while (0)
#define STSB(bufB)                                                               \
    asm volatile("st.shared.v4.f32 [%0], {%1,%2,%3,%4};"                         \
                 :: "r"(bdst + (bufB) * 5120), "f"(br0), "f"(br1), "f"(br2), "f"(br3))

    CPA(0, 0);
    CPA(1, 1);
    LDGB(0);
    STSB(0);
    LDGB(1);
    asm volatile("cp.async.wait_group 1;" ::: "memory");
    __syncthreads();

    int bufA = 0;
    for (int c = 0; c < nch; c++) {
        int bufB = c & 1;
        if (c + 2 < nch) {
            int tb = bufA + 2; if (tb >= 3) tb -= 3;
            CPA(c + 2, tb);
        }
        const unsigned abase = a_l + bufA * 10240;
        const unsigned bbase = b_l + bufB * 5120;
#pragma unroll
        for (int kk = 0; kk < 2; kk++) {
            unsigned a[2][4], b[2][4];
            ldm4(a[0], abase + kk * 32);
            ldm4(a[1], abase + 1280 + kk * 32);
            ldm4(b[0], bbase + kk * 32);
            ldm4(b[1], bbase + 1280 + kk * 32);
#pragma unroll
            for (int i = 0; i < 2; i++) {
                mma_tf32(acc[i][0], a[i][0], a[i][1], a[i][2], a[i][3], b[0][0], b[0][1]);
                mma_tf32(acc[i][1], a[i][0], a[i][1], a[i][2], a[i][3], b[0][2], b[0][3]);
                mma_tf32(acc[i][2], a[i][0], a[i][1], a[i][2], a[i][3], b[1][0], b[1][1]);
                mma_tf32(acc[i][3], a[i][0], a[i][1], a[i][2], a[i][3], b[1][2], b[1][3]);
            }
        }
        if (c < nch - 1) {
            STSB(bufB ^ 1);
            if (c + 2 < nch) {
                LDGB(c + 2);
                asm volatile("cp.async.wait_group 1;" ::: "memory");
            } else {
                asm volatile("cp.async.wait_group 0;" ::: "memory");
            }
            __syncthreads();
        }
        if (++bufA == 3) bufA = 0;
    }
#undef CPA
#undef LDGB
#undef STSB
}

// z-sliced GEMM (single A, per-slice B/C)
__global__ __launch_bounds__(256) void tf32gemm_kernel(
    const float* __restrict__ A0,
    const float* __restrict__ B0, const float* __restrict__ B1,
    const float* __restrict__ B2,
    void* __restrict__ C0, void* __restrict__ C1, void* __restrict__ C2,
    int bfmask, int Ndim, int Kdim)
{
    const float* Bp;
    void* Cp;
    switch (blockIdx.z) {
        case 0: Bp = B0; Cp = C0; break;
        case 1: Bp = B1; Cp = C1; break;
        default: Bp = B2; Cp = C2; break;
    }
    const bool bf16out = (bfmask >> blockIdx.z) & 1;

    __shared__ __align__(16) char smem_raw[40960];
    const unsigned sbase = (unsigned)__cvta_generic_to_shared(smem_raw);

    const int tid = threadIdx.x;
    const int bm = blockIdx.y * 128, bn = blockIdx.x * 64;
    const int lane = tid & 31;
    const int w = tid >> 5;
    const int wm = w & 3, wn = w >> 2;
    const int lq = lane >> 2, lr = lane & 3;

    const unsigned a_l = sbase + (wm * 32 + (lane & 15)) * 80 + (lane >> 4) * 16;
    const unsigned b_l = sbase + 30720 +
        (wn * 32 + (lane & 7) + ((lane >> 4) & 1) * 8) * 80 + ((lane >> 3) & 1) * 16;

    float acc[2][4][4];
#pragma unroll
    for (int i = 0; i < 2; i++)
#pragma unroll
        for (int j = 0; j < 4; j++)
#pragma unroll
            for (int u = 0; u < 4; u++) acc[i][j][u] = 0.f;

    gemm_phase(A0, Bp, Kdim, Ndim, sbase, tid, bm, bn, a_l, b_l, acc);

#pragma unroll
    for (int i = 0; i < 2; i++) {
#pragma unroll
        for (int j = 0; j < 4; j++) {
            int row = bm + wm * 32 + i * 16 + lq;
            int col = bn + wn * 32 + j * 8 + lr * 2;
            if (bf16out) {
                __nv_bfloat16* Cb = (__nv_bfloat16*)Cp;
                *(__nv_bfloat162*)(Cb + (size_t)row * Ndim + col) =
                    __float22bfloat162_rn(make_float2(acc[i][j][0], acc[i][j][1]));
                *(__nv_bfloat162*)(Cb + (size_t)(row + 8) * Ndim + col) =
                    __float22bfloat162_rn(make_float2(acc[i][j][2], acc[i][j][3]));
            } else {
                float* Cf = (float*)Cp;
                *(float2*)(Cf + (size_t)row * Ndim + col) =
                    make_float2(acc[i][j][0], acc[i][j][1]);
                *(float2*)(Cf + (size_t)(row + 8) * Ndim + col) =
                    make_float2(acc[i][j][2], acc[i][j][3]);
            }
        }
    }
}

// dual-phase GEMM: C = A@B (K=kd) + A2@B2 (K=kd2)
__global__ __launch_bounds__(256) void tf32gemm_dual_kernel(
    const float* __restrict__ A, const float* __restrict__ B,
    const float* __restrict__ A2, const float* __restrict__ B2,
    float* __restrict__ C, int Ndim, int kd, int kd2)
{
    __shared__ __align__(16) char smem_raw[40960];
    const unsigned sbase = (unsigned)__cvta_generic_to_shared(smem_raw);

    const int tid = threadIdx.x;
    const int bm = blockIdx.y * 128, bn = blockIdx.x * 64;
    const int lane = tid & 31;
    const int w = tid >> 5;
    const int wm = w & 3, wn = w >> 2;
    const int lq = lane >> 2, lr = lane & 3;

    const unsigned a_l = sbase + (wm * 32 + (lane & 15)) * 80 + (lane >> 4) * 16;
    const unsigned b_l = sbase + 30720 +
        (wn * 32 + (lane & 7) + ((lane >> 4) & 1) * 8) * 80 + ((lane >> 3) & 1) * 16;

    float acc[2][4][4];
#pragma unroll
    for (int i = 0; i < 2; i++)
#pragma unroll
        for (int j = 0; j < 4; j++)
#pragma unroll
            for (int u = 0; u < 4; u++) acc[i][j][u] = 0.f;

    gemm_phase(A, B, kd, Ndim, sbase, tid, bm, bn, a_l, b_l, acc);
    __syncthreads();
    gemm_phase(A2, B2, kd2, Ndim, sbase, tid, bm, bn, a_l, b_l, acc);

#pragma unroll
    for (int i = 0; i < 2; i++) {
#pragma unroll
        for (int j = 0; j < 4; j++) {
            int row = bm + wm * 32 + i * 16 + lq;
            int col = bn + wn * 32 + j * 8 + lr * 2;
            *(float2*)(C + (size_t)row * Ndim + col) =
                make_float2(acc[i][j][0], acc[i][j][1]);
            *(float2*)(C + (size_t)(row + 8) * Ndim + col) =
                make_float2(acc[i][j][2], acc[i][j][3]);
        }
    }
}

// ---------------- attention (rank-2 edge algebra + ILP-4, NO prefetch) ----------------
__device__ __forceinline__ float2 bf2f(unsigned u) {
    __nv_bfloat162 h = *reinterpret_cast<__nv_bfloat162*>(&u);
    return __bfloat1622float2(h);
}

__global__ __launch_bounds__(128) void attn_kernel(int r) {
    int j = blockIdx.x;
    int warp = threadIdx.x >> 5;
    int lane = threadIdx.x & 31;
    const int hd0 = warp * DD + lane * 4;
    const size_t jbase = (size_t)j * HO + hd0;

    float4 qv = *(const float4*)(g_q + jbase);
    float qr[4] = {qv.x, qv.y, qv.z, qv.w};
    float Mx[4], My[4];
#pragma unroll
    for (int u = 0; u < 4; u++) { Mx[u] = g_M[r][hd0 + u]; My[u] = g_M[r][HO + hd0 + u]; }
    const float qMx = qr[0] * Mx[0] + qr[1] * Mx[1] + qr[2] * Mx[2] + qr[3] * Mx[3];
    const float qMy = qr[0] * My[0] + qr[1] * My[1] + qr[2] * My[2] + qr[3] * My[3];

    float m, den = 1.f, acc[4];
    float cx = 0.f, cy = 0.f;
    {
        uint2 kr = *(const uint2*)(g_kb + jbase);
        uint2 vr = *(const uint2*)(g_vb + jbase);
        float2 k01 = bf2f(kr.x), k23 = bf2f(kr.y);
        float2 v01 = bf2f(vr.x), v23 = bf2f(vr.y);
        float part = qr[0] * k01.x + qr[1] * k01.y + qr[2] * k23.x + qr[3] * k23.y;
#pragma unroll
        for (int o = 16; o; o >>= 1) part += __shfl_xor_sync(0xffffffffu, part, o);
        m = part * SCALE;
        acc[0] = v01.x; acc[1] = v01.y; acc[2] = v23.x; acc[3] = v23.y;
    }

    int e0 = g_indptr[j], e1 = g_indptr[j + 1];
    int ei = e0;
    for (; ei + 4 <= e1; ei += 4) {
        float2 rr[4];
        uint2 kr[4], vr[4];
#pragma unroll
        for (int i = 0; i < 4; i++) {
            int s = g_esrc[ei + i];
            rr[i] = g_erel[ei + i];
            kr[i] = *(const uint2*)(g_kb + (size_t)s * HO + hd0);
            vr[i] = *(const uint2*)(g_vb + (size_t)s * HO + hd0);
        }
        float part[4];
#pragma unroll
        for (int i = 0; i < 4; i++) {
            float2 k01 = bf2f(kr[i].x), k23 = bf2f(kr[i].y);
            part[i] = qr[0] * k01.x + qr[1] * k01.y + qr[2] * k23.x + qr[3] * k23.y
                    + rr[i].x * qMx + rr[i].y * qMy;
        }
#pragma unroll
        for (int o = 16; o; o >>= 1) {
#pragma unroll
            for (int i = 0; i < 4; i++)
                part[i] += __shfl_xor_sync(0xffffffffu, part[i], o);
        }
        float a0 = part[0] * SCALE, a1 = part[1] * SCALE;
        float a2 = part[2] * SCALE, a3 = part[3] * SCALE;
        float mb = fmaxf(fmaxf(a0, a1), fmaxf(a2, a3));
        float mn = fmaxf(m, mb);
        float fold = __expf(m - mn);
        float w0 = __expf(a0 - mn), w1 = __expf(a1 - mn);
        float w2 = __expf(a2 - mn), w3 = __expf(a3 - mn);
        den = den * fold + (w0 + w1 + w2 + w3);
        cx = cx * fold + (w0 * rr[0].x + w1 * rr[1].x + w2 * rr[2].x + w3 * rr[3].x);
        cy = cy * fold + (w0 * rr[0].y + w1 * rr[1].y + w2 * rr[2].y + w3 * rr[3].y);
        float2 v01[4], v23[4];
#pragma unroll
        for (int i = 0; i < 4; i++) { v01[i] = bf2f(vr[i].x); v23[i] = bf2f(vr[i].y); }
        acc[0] = acc[0] * fold + (w0 * v01[0].x + w1 * v01[1].x + w2 * v01[2].x + w3 * v01[3].x);
        acc[1] = acc[1] * fold + (w0 * v01[0].y + w1 * v01[1].y + w2 * v01[2].y + w3 * v01[3].y);
        acc[2] = acc[2] * fold + (w0 * v23[0].x + w1 * v23[1].x + w2 * v23[2].x + w3 * v23[3].x);
        acc[3] = acc[3] * fold + (w0 * v23[0].y + w1 * v23[1].y + w2 * v23[2].y + w3 * v23[3].y);
        m = mn;
    }
    for (; ei < e1; ++ei) {
        int s = g_esrc[ei];
        float2 rr = g_erel[ei];
        uint2 kr = *(const uint2*)(g_kb + (size_t)s * HO + hd0);
        uint2 vr = *(const uint2*)(g_vb + (size_t)s * HO + hd0);
        float2 k01 = bf2f(kr.x), k23 = bf2f(kr.y);
        float part = qr[0] * k01.x + qr[1] * k01.y + qr[2] * k23.x + qr[3] * k23.y
                   + rr.x * qMx + rr.y * qMy;
#pragma unroll
        for (int o = 16; o; o >>= 1) part += __shfl_xor_sync(0xffffffffu, part, o);
        float alpha = part * SCALE;
        float mn = fmaxf(m, alpha);
        float fold = __expf(m - mn);
        float wgt = __expf(alpha - mn);
        den = den * fold + wgt;
        cx = cx * fold + wgt * rr.x;
        cy = cy * fold + wgt * rr.y;
        float2 v01 = bf2f(vr.x), v23 = bf2f(vr.y);
        acc[0] = acc[0] * fold + wgt * v01.x;
        acc[1] = acc[1] * fold + wgt * v01.y;
        acc[2] = acc[2] * fold + wgt * v23.x;
        acc[3] = acc[3] * fold + wgt * v23.y;
        m = mn;
    }

    float inv = 1.f / den;
#pragma unroll
    for (int u = 0; u < 4; u++)
        acc[u] = (acc[u] + cx * Mx[u] + cy * My[u]) * inv;
    *(float4*)(g_t + jbase) = make_float4(tf32r(acc[0]), tf32r(acc[1]),
                                          tf32r(acc[2]), tf32r(acc[3]));
}

// x_out = tf32(rmsnorm(y1 + x_in, ln_w))
__global__ __launch_bounds__(128) void rmsres_kernel(const float* __restrict__ lnw) {
    int j = blockIdx.x, d = threadIdx.x;
    size_t i = (size_t)j * DD + d;
    float val = g_y1[i] + g_x[i];
    float ss = val * val;
#pragma unroll
    for (int off = 16; off; off >>= 1) ss += __shfl_xor_sync(0xffffffffu, ss, off);
    __shared__ float w4[4];
    if ((threadIdx.x & 31) == 0) w4[threadIdx.x >> 5] = ss;
    __syncthreads();
    float tot = w4[0] + w4[1] + w4[2] + w4[3];
    float r = rsqrtf(tot / (float)DD + EPS);
    g_x[i] = tf32r(val * r * lnw[d]);
}

// out = rmsnorm(y, ln_f)
__global__ __launch_bounds__(64) void rmsfinal_kernel(const float* __restrict__ y,
                                                      const float* __restrict__ lnf,
                                                      float* __restrict__ out) {
    int j = blockIdx.x, d = threadIdx.x;
    float val = y[(size_t)j * AA + d];
    float ss = val * val;
#pragma unroll
    for (int off = 16; off; off >>= 1) ss += __shfl_xor_sync(0xffffffffu, ss, off);
    __shared__ float w2[2];
    if ((threadIdx.x & 31) == 0) w2[threadIdx.x >> 5] = ss;
    __syncthreads();
    float tot = w2[0] + w2[1];
    float r = rsqrtf(tot / (float)AA + EPS);
    out[(size_t)j * AA + d] = val * r * lnf[d];
}

// ---------------- launch ----------------
extern "C" void kernel_launch(void* const* d_in, const int* in_sizes, int n_in,
                              void* d_out, int out_size) {
    const float* node_features = (const float*)d_in[0];
    const int*   ids           = (const int*)d_in[1];
    const float* rel           = (const float*)d_in[2];
    const float* We_emb        = (const float*)d_in[3];
    const float* Wq            = (const float*)d_in[4];
    const float* Wk            = (const float*)d_in[5];
    const float* Wv            = (const float*)d_in[6];
    const float* Wedge         = (const float*)d_in[7];
    const float* Wskip         = (const float*)d_in[8];
    const float* Wout          = (const float*)d_in[9];
    const float* lnw           = (const float*)d_in[10];
    const float* Wact          = (const float*)d_in[11];
    const float* lnf           = (const float*)d_in[12];
    float* out = (float*)d_out;

    float *xp, *qp, *tp, *y1p, *wswp, *wqcp, *wkcp, *wvcp, *wocp, *wacp;
    __nv_bfloat16 *kbp, *vbp;
    cudaGetSymbolAddress((void**)&xp, g_x);
    cudaGetSymbolAddress((void**)&qp, g_q);
    cudaGetSymbolAddress((void**)&kbp, g_kb);
    cudaGetSymbolAddress((void**)&vbp, g_vb);
    cudaGetSymbolAddress((void**)&tp, g_t);
    cudaGetSymbolAddress((void**)&y1p, g_y1);
    cudaGetSymbolAddress((void**)&wswp, g_wsw);
    cudaGetSymbolAddress((void**)&wqcp, g_wqc);
    cudaGetSymbolAddress((void**)&wkcp, g_wkc);
    cudaGetSymbolAddress((void**)&wvcp, g_wvc);
    cudaGetSymbolAddress((void**)&wocp, g_woc);
    cudaGetSymbolAddress((void**)&wacp, g_wac);

    // side stream + events, created once on the (uncaptured) correctness call
    static cudaStream_t s1 = nullptr;
    static cudaEvent_t evFork = nullptr, evJoin = nullptr;
    if (!s1) {
        cudaStreamCreateWithFlags(&s1, cudaStreamNonBlocking);
        cudaEventCreateWithFlags(&evFork, cudaEventDisableTiming);
        cudaEventCreateWithFlags(&evJoin, cudaEventDisableTiming);
    }

    dim3 gqkv(HO / 64, NN / 128, 3);
    dim3 gdual(DD / 64, NN / 128, 1);
    dim3 gf(AA / 64, NN / 128, 1);

    // fork: edge build + prep on side stream, conv + QKV r0 on main
    cudaEventRecord(evFork, 0);
    cudaStreamWaitEvent(s1, evFork, 0);

    zero_detect_kernel<<<(NN + 255) / 256, 256, 0, s1>>>(ids);
    count_kernel<<<(ENBR + 255) / 256, 256, 0, s1>>>(ids);
    scan_kernel<<<1, 1024, 0, s1>>>();
    scatter_kernel<<<(ENBR + 255) / 256, 256, 0, s1>>>(ids, rel);
    prep_kernel<<<dim3(DD + 4, RR), 128, 0, s1>>>(We_emb, Wedge, Wskip, Wout);
    cudaEventRecord(evJoin, s1);

    conv_kernel<<<(NN * DD + 255) / 256, 256>>>(Wq, Wk, Wv, Wout, Wact, node_features);
    tf32gemm_kernel<<<gqkv, 256>>>(xp, wqcp, wkcp, wvcp,
                                   qp, kbp, vbp, /*bfmask=*/0b110, HO, DD);
    cudaStreamWaitEvent(0, evJoin, 0);   // join before attention needs edges/M

    for (int r = 0; r < RR; r++) {
        if (r > 0) {
            const float* wq = wqcp + (size_t)r * DD * HO;
            const float* wk = wkcp + (size_t)r * DD * HO;
            const float* wv = wvcp + (size_t)r * DD * HO;
            tf32gemm_kernel<<<gqkv, 256>>>(xp, wq, wk, wv,
                                           qp, kbp, vbp, 0b110, HO, DD);
        }
        attn_kernel<<<NN, 128>>>(r);
        // y1 = agg @ Wout (K=512) + x @ Wsw (K=128)
        tf32gemm_dual_kernel<<<gdual, 256>>>(tp, wocp + (size_t)r * HO * DD,
                                             xp, wswp + (size_t)r * DD * DD,
                                             y1p, DD, HO, DD);
        rmsres_kernel<<<NN, DD>>>(lnw + (size_t)r * DD);
    }

    tf32gemm_kernel<<<gf, 256>>>(xp, wacp, wacp, wacp,
                                 y1p, y1p, y1p, /*bfmask=*/0, AA, DD);
    rmsfinal_kernel<<<NN, AA>>>(y1p, lnf, out);
}

// round 14
// speedup vs baseline: 1.1142x; 1.0323x over previous
#include <cuda_runtime.h>
#include <cuda_bf16.h>
#include <stdint.h>
#include <math.h>

// Problem constants
#define BB 8
#define CC 1024
#define LL 32
#define NN 8192          // B*C
#define DD 128
#define HH 4
#define HO 512           // H*D
#define RR 3
#define AA 64
#define ENBR 262144      // N*L
#define EPS 1e-5f
#define SCALE 0.08838834764831845f   // 1/sqrt(128)

// ---------------- static device scratch ----------------
__device__ __align__(128) float g_x[NN * DD];
__device__ __align__(128) float g_q[NN * HO];
__device__ __align__(128) __nv_bfloat16 g_kb[NN * HO];
__device__ __align__(128) __nv_bfloat16 g_vb[NN * HO];
__device__ __align__(128) float g_t[NN * HO];
__device__ __align__(128) float g_y1[NN * DD];
__device__ __align__(128) float g_M[RR][2 * HO];
__device__ __align__(128) float g_wsw[RR][DD * DD];
__device__ __align__(128) float g_wqc[RR * DD * HO];
__device__ __align__(128) float g_wkc[RR * DD * HO];
__device__ __align__(128) float g_wvc[RR * DD * HO];
__device__ __align__(128) float g_woc[RR * HO * DD];
__device__ __align__(128) float g_wac[DD * AA];
__device__ int   g_indptr[NN + 1];
__device__ int   g_cnt[NN];
__device__ int   g_cursor[NN];
__device__ int   g_esrc[ENBR];
__device__ __align__(16) float2 g_erel[ENBR];
__device__ int   g_fmt[1];

__device__ __forceinline__ unsigned f2tf32(float x) {
    unsigned r;
    asm("cvt.rna.tf32.f32 %0, %1;" : "=r"(r) : "f"(x));
    return r;
}
__device__ __forceinline__ float tf32r(float x) { return __uint_as_float(f2tf32(x)); }

// ---------------- setup kernels ----------------
__global__ void conv_kernel(const float* __restrict__ Wq, const float* __restrict__ Wk,
                            const float* __restrict__ Wv, const float* __restrict__ Wout,
                            const float* __restrict__ Wact, const float* __restrict__ nf) {
    int i = blockIdx.x * blockDim.x + threadIdx.x;
    const int S = RR * DD * HO;
    if (i < S) {
        g_wqc[i] = tf32r(Wq[i]);
        g_wkc[i] = tf32r(Wk[i]);
        g_wvc[i] = tf32r(Wv[i]);
        g_woc[i] = tf32r(Wout[i]);
        if (i < DD * AA) g_wac[i] = tf32r(Wact[i]);
    }
    if (i < NN * DD) g_x[i] = tf32r(nf[i]);
}

__global__ void zero_detect_kernel(const int* __restrict__ ids) {
    int i = blockIdx.x * blockDim.x + threadIdx.x;
    if (i < NN) g_cnt[i] = 0;
    if (blockIdx.x == 0 && threadIdx.x < 32) {
        int nz = 0;
        for (int k2 = threadIdx.x; k2 < 64; k2 += 32)
            nz |= (ids[2 * k2 + 1] != 0);
        nz = __any_sync(0xffffffffu, nz);
        if (threadIdx.x == 0) g_fmt[0] = nz ? 0 : 1;
    }
}

__device__ __forceinline__ int load_id(const int* __restrict__ ids, int idx, int fmt64) {
    return fmt64 ? ids[2 * idx] : ids[idx];
}

__global__ void count_kernel(const int* __restrict__ ids) {
    int idx = blockIdx.x * blockDim.x + threadIdx.x;
    if (idx >= ENBR) return;
    int fmt = g_fmt[0];
    int id = load_id(ids, idx, fmt);
    int n = idx >> 5;
    int dst = (n & ~(CC - 1)) | id;
    atomicAdd(&g_cnt[dst], 1);
}

// warp-shuffle scan
__global__ void scan_kernel() {
    __shared__ int wsum[32];
    int t = threadIdx.x;
    int lane = t & 31, wid = t >> 5;
    int local[8];
    int s = 0;
#pragma unroll
    for (int i = 0; i < 8; i++) { local[i] = g_cnt[t * 8 + i]; s += local[i]; }
    int v = s;
#pragma unroll
    for (int off = 1; off < 32; off <<= 1) {
        int u = __shfl_up_sync(0xffffffffu, v, off);
        if (lane >= off) v += u;
    }
    if (lane == 31) wsum[wid] = v;
    __syncthreads();
    if (wid == 0) {
        int wv = wsum[lane];
#pragma unroll
        for (int off = 1; off < 32; off <<= 1) {
            int u = __shfl_up_sync(0xffffffffu, wv, off);
            if (lane >= off) wv += u;
        }
        wsum[lane] = wv;
    }
    __syncthreads();
    int base = (wid ? wsum[wid - 1] : 0) + v - s;
#pragma unroll
    for (int i = 0; i < 8; i++) {
        g_indptr[t * 8 + i] = base;
        g_cursor[t * 8 + i] = base;
        base += local[i];
    }
    if (t == 1023) g_indptr[NN] = base;
}

__global__ void scatter_kernel(const int* __restrict__ ids, const float* __restrict__ rc) {
    int idx = blockIdx.x * blockDim.x + threadIdx.x;
    if (idx >= ENBR) return;
    int fmt = g_fmt[0];
    int id = load_id(ids, idx, fmt);
    int n = idx >> 5;
    int l = idx & 31;
    int dst = (n & ~(CC - 1)) | id;
    int pos = atomicAdd(&g_cursor[dst], 1);
    g_esrc[pos] = n;
    g_erel[pos] = make_float2(rc[n * (2 * LL) + 2 * l], rc[n * (2 * LL) + 2 * l + 1]);
}

__global__ __launch_bounds__(128) void prep_kernel(
    const float* __restrict__ We, const float* __restrict__ Wedge,
    const float* __restrict__ Wskip, const float* __restrict__ Wout)
{
    int r = blockIdx.y;
    const float* Wer = We + (size_t)r * 2 * DD;
    const float* Wedger = Wedge + (size_t)r * DD * HO;
    const float* Wskipr = Wskip + (size_t)r * DD * HO;
    const float* Woutr = Wout + (size_t)r * HO * DD;
    int b = blockIdx.x;
    if (b < DD) {
        __shared__ float row[HO];
        for (int i = threadIdx.x; i < HO; i += 128) row[i] = Wskipr[b * HO + i];
        __syncthreads();
        float s = 0.f;
        for (int k2 = 0; k2 < HO; k2++) s += row[k2] * Woutr[k2 * DD + threadIdx.x];
        g_wsw[r][b * DD + threadIdx.x] = tf32r(s);
    } else {
        int o = (b - DD) * 128 + threadIdx.x;
        float s0 = 0.f, s1 = 0.f;
        for (int d = 0; d < DD; d++) {
            float w = Wedger[d * HO + o];
            s0 += Wer[d] * w;
            s1 += Wer[DD + d] * w;
        }
        g_M[r][o] = s0;
        g_M[r][HO + o] = s1;
    }
}

// ---------------- tf32 GEMM core (cp.async + ldmatrix) ----------------
__device__ __forceinline__ void mma_tf32(float* c, unsigned a0, unsigned a1, unsigned a2,
                                         unsigned a3, unsigned b0, unsigned b1) {
    asm volatile(
        "mma.sync.aligned.m16n8k8.row.col.f32.tf32.tf32.f32 "
        "{%0,%1,%2,%3}, {%4,%5,%6,%7}, {%8,%9}, {%0,%1,%2,%3};"
        : "+f"(c[0]), "+f"(c[1]), "+f"(c[2]), "+f"(c[3])
        : "r"(a0), "r"(a1), "r"(a2), "r"(a3), "r"(b0), "r"(b1));
}

__device__ __forceinline__ void ldm4(unsigned* r, unsigned addr) {
    asm volatile("ldmatrix.sync.aligned.m8n8.x4.shared.b16 {%0,%1,%2,%3}, [%4];"
                 : "=r"(r[0]), "=r"(r[1]), "=r"(r[2]), "=r"(r[3]) : "r"(addr));
}

__device__ __forceinline__ void gemm_phase(
    const float* __restrict__ Ap, const float* __restrict__ Bp, int kd, int Ndim,
    unsigned sbase, int tid, int bm, int bn,
    unsigned a_l, unsigned b_l, float acc[2][4][4])
{
    const int arow = tid >> 2, akq = tid & 3;
    const float* asrc = Ap + (size_t)(bm + arow) * kd + akq * 4;
    const size_t asrc2 = (size_t)64 * kd;
    const unsigned adst = sbase + arow * 80 + akq * 16;

    const int bnn = tid & 63, bk4 = (tid >> 6) * 4;
    const float* bsrc = Bp + (size_t)bk4 * Ndim + bn + bnn;
    const unsigned bdst = sbase + 30720 + bnn * 80 + bk4 * 4;
    float br0, br1, br2, br3;
    const int nch = kd >> 4;

#define CPA(c, bufA) do {                                                        \
    const float* s0_ = asrc + (c) * 16;                                          \
    unsigned d0_ = adst + (bufA) * 10240;                                        \
    asm volatile("cp.async.cg.shared.global [%0],[%1],16;\n"                     \
                 "cp.async.cg.shared.global [%2],[%3],16;\n"                     \
                 "cp.async.commit_group;\n"                                      \
                 :: "r"(d0_), "l"(s0_), "r"(d0_ + 64 * 80), "l"(s0_ + asrc2));   \
} while (0)
#define LDGB(c) do {                                                             \
    const float* p_ = bsrc + (size_t)(c) * 16 * Ndim;                            \
    br0 = __ldg(p_); br1 = __ldg(p_ + Ndim);                                     \
    br2 = __ldg(p_ + 2 * (size_t)Ndim); br3 = __ldg(p_ + 3 * (size_t)Ndim);      \
} while (0)
#define STSB(bufB)                                                               \
    asm volatile("st.shared.v4.f32 [%0], {%1,%2,%3,%4};"                         \
                 :: "r"(bdst + (bufB) * 5120), "f"(br0), "f"(br1), "f"(br2), "f"(br3))

    CPA(0, 0);
    CPA(1, 1);
    LDGB(0);
    STSB(0);
    LDGB(1);
    asm volatile("cp.async.wait_group 1;" ::: "memory");
    __syncthreads();

    int bufA = 0;
    for (int c = 0; c < nch; c++) {
        int bufB = c & 1;
        if (c + 2 < nch) {
            int tb = bufA + 2; if (tb >= 3) tb -= 3;
            CPA(c + 2, tb);
        }
        const unsigned abase = a_l + bufA * 10240;
        const unsigned bbase = b_l + bufB * 5120;
#pragma unroll
        for (int kk = 0; kk < 2; kk++) {
            unsigned a[2][4], b[2][4];
            ldm4(a[0], abase + kk * 32);
            ldm4(a[1], abase + 1280 + kk * 32);
            ldm4(b[0], bbase + kk * 32);
            ldm4(b[1], bbase + 1280 + kk * 32);
#pragma unroll
            for (int i = 0; i < 2; i++) {
                mma_tf32(acc[i][0], a[i][0], a[i][1], a[i][2], a[i][3], b[0][0], b[0][1]);
                mma_tf32(acc[i][1], a[i][0], a[i][1], a[i][2], a[i][3], b[0][2], b[0][3]);
                mma_tf32(acc[i][2], a[i][0], a[i][1], a[i][2], a[i][3], b[1][0], b[1][1]);
                mma_tf32(acc[i][3], a[i][0], a[i][1], a[i][2], a[i][3], b[1][2], b[1][3]);
            }
        }
        if (c < nch - 1) {
            STSB(bufB ^ 1);
            if (c + 2 < nch) {
                LDGB(c + 2);
                asm volatile("cp.async.wait_group 1;" ::: "memory");
            } else {
                asm volatile("cp.async.wait_group 0;" ::: "memory");
            }
            __syncthreads();
        }
        if (++bufA == 3) bufA = 0;
    }
#undef CPA
#undef LDGB
#undef STSB
}

// z-sliced GEMM (single A, per-slice B/C)
__global__ __launch_bounds__(256) void tf32gemm_kernel(
    const float* __restrict__ A0,
    const float* __restrict__ B0, const float* __restrict__ B1,
    const float* __restrict__ B2,
    void* __restrict__ C0, void* __restrict__ C1, void* __restrict__ C2,
    int bfmask, int Ndim, int Kdim)
{
    const float* Bp;
    void* Cp;
    switch (blockIdx.z) {
        case 0: Bp = B0; Cp = C0; break;
        case 1: Bp = B1; Cp = C1; break;
        default: Bp = B2; Cp = C2; break;
    }
    const bool bf16out = (bfmask >> blockIdx.z) & 1;

    __shared__ __align__(16) char smem_raw[40960];
    const unsigned sbase = (unsigned)__cvta_generic_to_shared(smem_raw);

    const int tid = threadIdx.x;
    const int bm = blockIdx.y * 128, bn = blockIdx.x * 64;
    const int lane = tid & 31;
    const int w = tid >> 5;
    const int wm = w & 3, wn = w >> 2;
    const int lq = lane >> 2, lr = lane & 3;

    const unsigned a_l = sbase + (wm * 32 + (lane & 15)) * 80 + (lane >> 4) * 16;
    const unsigned b_l = sbase + 30720 +
        (wn * 32 + (lane & 7) + ((lane >> 4) & 1) * 8) * 80 + ((lane >> 3) & 1) * 16;

    float acc[2][4][4];
#pragma unroll
    for (int i = 0; i < 2; i++)
#pragma unroll
        for (int j = 0; j < 4; j++)
#pragma unroll
            for (int u = 0; u < 4; u++) acc[i][j][u] = 0.f;

    gemm_phase(A0, Bp, Kdim, Ndim, sbase, tid, bm, bn, a_l, b_l, acc);

#pragma unroll
    for (int i = 0; i < 2; i++) {
#pragma unroll
        for (int j = 0; j < 4; j++) {
            int row = bm + wm * 32 + i * 16 + lq;
            int col = bn + wn * 32 + j * 8 + lr * 2;
            if (bf16out) {
                __nv_bfloat16* Cb = (__nv_bfloat16*)Cp;
                *(__nv_bfloat162*)(Cb + (size_t)row * Ndim + col) =
                    __float22bfloat162_rn(make_float2(acc[i][j][0], acc[i][j][1]));
                *(__nv_bfloat162*)(Cb + (size_t)(row + 8) * Ndim + col) =
                    __float22bfloat162_rn(make_float2(acc[i][j][2], acc[i][j][3]));
            } else {
                float* Cf = (float*)Cp;
                *(float2*)(Cf + (size_t)row * Ndim + col) =
                    make_float2(acc[i][j][0], acc[i][j][1]);
                *(float2*)(Cf + (size_t)(row + 8) * Ndim + col) =
                    make_float2(acc[i][j][2], acc[i][j][3]);
            }
        }
    }
}

// dual-phase GEMM: C = A@B (K=kd) + A2@B2 (K=kd2)
__global__ __launch_bounds__(256) void tf32gemm_dual_kernel(
    const float* __restrict__ A, const float* __restrict__ B,
    const float* __restrict__ A2, const float* __restrict__ B2,
    float* __restrict__ C, int Ndim, int kd, int kd2)
{
    __shared__ __align__(16) char smem_raw[40960];
    const unsigned sbase = (unsigned)__cvta_generic_to_shared(smem_raw);

    const int tid = threadIdx.x;
    const int bm = blockIdx.y * 128, bn = blockIdx.x * 64;
    const int lane = tid & 31;
    const int w = tid >> 5;
    const int wm = w & 3, wn = w >> 2;
    const int lq = lane >> 2, lr = lane & 3;

    const unsigned a_l = sbase + (wm * 32 + (lane & 15)) * 80 + (lane >> 4) * 16;
    const unsigned b_l = sbase + 30720 +
        (wn * 32 + (lane & 7) + ((lane >> 4) & 1) * 8) * 80 + ((lane >> 3) & 1) * 16;

    float acc[2][4][4];
#pragma unroll
    for (int i = 0; i < 2; i++)
#pragma unroll
        for (int j = 0; j < 4; j++)
#pragma unroll
            for (int u = 0; u < 4; u++) acc[i][j][u] = 0.f;

    gemm_phase(A, B, kd, Ndim, sbase, tid, bm, bn, a_l, b_l, acc);
    __syncthreads();
    gemm_phase(A2, B2, kd2, Ndim, sbase, tid, bm, bn, a_l, b_l, acc);

#pragma unroll
    for (int i = 0; i < 2; i++) {
#pragma unroll
        for (int j = 0; j < 4; j++) {
            int row = bm + wm * 32 + i * 16 + lq;
            int col = bn + wn * 32 + j * 8 + lr * 2;
            *(float2*)(C + (size_t)row * Ndim + col) =
                make_float2(acc[i][j][0], acc[i][j][1]);
            *(float2*)(C + (size_t)(row + 8) * Ndim + col) =
                make_float2(acc[i][j][2], acc[i][j][3]);
        }
    }
}

// ---------------- attention: warp = edge-quarter, lanes cover all 4 heads ----------------
// lane l: head h=l>>3, dims (l&7)*16 .. +16 of that head. 8-lane group = one head's 128 dims.
// Each warp runs online softmax over its strided quarter of edges; 4 partial states merged
// exactly at the end (split-softmax merge).
__device__ __forceinline__ float2 bf2f(unsigned u) {
    __nv_bfloat162 h = *reinterpret_cast<__nv_bfloat162*>(&u);
    return __bfloat1622float2(h);
}

__device__ __forceinline__ float dot16(const float* q, uint4 a, uint4 b) {
    float s = 0.f;
    const unsigned* wa = (const unsigned*)&a;
#pragma unroll
    for (int i = 0; i < 4; i++) {
        float2 f = bf2f(wa[i]);
        s += q[2 * i] * f.x + q[2 * i + 1] * f.y;
    }
    const unsigned* wb = (const unsigned*)&b;
#pragma unroll
    for (int i = 0; i < 4; i++) {
        float2 f = bf2f(wb[i]);
        s += q[8 + 2 * i] * f.x + q[9 + 2 * i] * f.y;
    }
    return s;
}

__device__ __forceinline__ void axpy16(float* acc, float fold, float w, uint4 a, uint4 b) {
    const unsigned* wa = (const unsigned*)&a;
#pragma unroll
    for (int i = 0; i < 4; i++) {
        float2 f = bf2f(wa[i]);
        acc[2 * i]     = acc[2 * i] * fold + w * f.x;
        acc[2 * i + 1] = acc[2 * i + 1] * fold + w * f.y;
    }
    const unsigned* wb = (const unsigned*)&b;
#pragma unroll
    for (int i = 0; i < 4; i++) {
        float2 f = bf2f(wb[i]);
        acc[8 + 2 * i] = acc[8 + 2 * i] * fold + w * f.x;
        acc[9 + 2 * i] = acc[9 + 2 * i] * fold + w * f.y;
    }
}

__global__ __launch_bounds__(128) void attn_kernel(int r) {
    const int j = blockIdx.x;
    const int tid = threadIdx.x;
    const int warp = tid >> 5, lane = tid & 31;
    const int h = lane >> 3, sub = lane & 7;
    const int hd0 = h * DD + sub * 16;
    const size_t jbase = (size_t)j * HO + hd0;

    // q: 16 floats
    float qr[16];
    {
        const float4* qp4 = (const float4*)(g_q + jbase);
#pragma unroll
        for (int i = 0; i < 4; i++) {
            float4 v = qp4[i];
            qr[i * 4 + 0] = v.x; qr[i * 4 + 1] = v.y;
            qr[i * 4 + 2] = v.z; qr[i * 4 + 3] = v.w;
        }
    }
    // per-head q·Mx, q·My (reduced within 8-lane group)
    float qMx = 0.f, qMy = 0.f;
    {
        const float* mx = g_M[r] + hd0;
        const float* my = g_M[r] + HO + hd0;
#pragma unroll
        for (int i = 0; i < 16; i++) { qMx += qr[i] * mx[i]; qMy += qr[i] * my[i]; }
#pragma unroll
        for (int o = 1; o < 8; o <<= 1) {
            qMx += __shfl_xor_sync(0xffffffffu, qMx, o);
            qMy += __shfl_xor_sync(0xffffffffu, qMy, o);
        }
    }

    float m = -1e30f, den = 0.f, cx = 0.f, cy = 0.f;
    float acc[16];
#pragma unroll
    for (int i = 0; i < 16; i++) acc[i] = 0.f;

    if (warp == 0) {
        // self edge (edge_attr = 0)
        uint4 k0 = *(const uint4*)(g_kb + jbase);
        uint4 k1 = *(const uint4*)(g_kb + jbase + 8);
        uint4 v0 = *(const uint4*)(g_vb + jbase);
        uint4 v1 = *(const uint4*)(g_vb + jbase + 8);
        float part = dot16(qr, k0, k1);
#pragma unroll
        for (int o = 1; o < 8; o <<= 1) part += __shfl_xor_sync(0xffffffffu, part, o);
        m = part * SCALE;
        den = 1.f;
        axpy16(acc, 0.f, 1.f, v0, v1);
    }

    const int e0 = g_indptr[j], e1 = g_indptr[j + 1];
    for (int ei = e0 + warp; ei < e1; ei += 4) {
        int s = g_esrc[ei];
        float2 rr = g_erel[ei];
        const size_t sb = (size_t)s * HO + hd0;
        uint4 k0 = *(const uint4*)(g_kb + sb);
        uint4 k1 = *(const uint4*)(g_kb + sb + 8);
        uint4 v0 = *(const uint4*)(g_vb + sb);
        uint4 v1 = *(const uint4*)(g_vb + sb + 8);
        float part = dot16(qr, k0, k1) + (rr.x * qMx + rr.y * qMy) * 0.125f;
        // note: qMx/qMy were reduced over 8 lanes, so the rr term would be counted 8x
        // after the reduction below; pre-scale by 1/8 so the post-reduction value is exact.
#pragma unroll
        for (int o = 1; o < 8; o <<= 1) part += __shfl_xor_sync(0xffffffffu, part, o);
        float alpha = part * SCALE;
        float mn = fmaxf(m, alpha);
        float fold = __expf(m - mn);
        float w = __expf(alpha - mn);
        den = den * fold + w;
        cx = cx * fold + w * rr.x;
        cy = cy * fold + w * rr.y;
        axpy16(acc, fold, w, v0, v1);
        m = mn;
    }

    // merge 4 warp states (split-softmax)
    __shared__ float s_m[4][4], s_den[4][4], s_cx[4][4], s_cy[4][4];
    __shared__ float s_acc[4][HO];
    if (sub == 0) {
        s_m[warp][h] = m; s_den[warp][h] = den;
        s_cx[warp][h] = cx; s_cy[warp][h] = cy;
    }
#pragma unroll
    for (int i = 0; i < 4; i++)
        *(float4*)&s_acc[warp][hd0 + i * 4] =
            make_float4(acc[i * 4], acc[i * 4 + 1], acc[i * 4 + 2], acc[i * 4 + 3]);
    __syncthreads();

    const int d = tid * 4;        // 0..508
    const int hh = tid >> 5;      // head of dims d..d+3
    float M = fmaxf(fmaxf(s_m[0][hh], s_m[1][hh]), fmaxf(s_m[2][hh], s_m[3][hh]));
    float f0 = __expf(s_m[0][hh] - M), f1 = __expf(s_m[1][hh] - M);
    float f2 = __expf(s_m[2][hh] - M), f3 = __expf(s_m[3][hh] - M);
    float dtot = s_den[0][hh] * f0 + s_den[1][hh] * f1 + s_den[2][hh] * f2 + s_den[3][hh] * f3;
    float cxT = s_cx[0][hh] * f0 + s_cx[1][hh] * f1 + s_cx[2][hh] * f2 + s_cx[3][hh] * f3;
    float cyT = s_cy[0][hh] * f0 + s_cy[1][hh] * f1 + s_cy[2][hh] * f2 + s_cy[3][hh] * f3;
    float inv = 1.f / dtot;
    const float* mx = g_M[r] + d;
    const float* my = g_M[r] + HO + d;
    float o4[4];
#pragma unroll
    for (int i = 0; i < 4; i++) {
        float a = s_acc[0][d + i] * f0 + s_acc[1][d + i] * f1 +
                  s_acc[2][d + i] * f2 + s_acc[3][d + i] * f3;
        o4[i] = tf32r((a + cxT * mx[i] + cyT * my[i]) * inv);
    }
    *(float4*)(g_t + (size_t)j * HO + d) = make_float4(o4[0], o4[1], o4[2], o4[3]);
}

// x_out = tf32(rmsnorm(y1 + x_in, ln_w))
__global__ __launch_bounds__(128) void rmsres_kernel(const float* __restrict__ lnw) {
    int j = blockIdx.x, d = threadIdx.x;
    size_t i = (size_t)j * DD + d;
    float val = g_y1[i] + g_x[i];
    float ss = val * val;
#pragma unroll
    for (int off = 16; off; off >>= 1) ss += __shfl_xor_sync(0xffffffffu, ss, off);
    __shared__ float w4[4];
    if ((threadIdx.x & 31) == 0) w4[threadIdx.x >> 5] = ss;
    __syncthreads();
    float tot = w4[0] + w4[1] + w4[2] + w4[3];
    float r = rsqrtf(tot / (float)DD + EPS);
    g_x[i] = tf32r(val * r * lnw[d]);
}

// out = rmsnorm(y, ln_f)
__global__ __launch_bounds__(64) void rmsfinal_kernel(const float* __restrict__ y,
                                                      const float* __restrict__ lnf,
                                                      float* __restrict__ out) {
    int j = blockIdx.x, d = threadIdx.x;
    float val = y[(size_t)j * AA + d];
    float ss = val * val;
#pragma unroll
    for (int off = 16; off; off >>= 1) ss += __shfl_xor_sync(0xffffffffu, ss, off);
    __shared__ float w2[2];
    if ((threadIdx.x & 31) == 0) w2[threadIdx.x >> 5] = ss;
    __syncthreads();
    float tot = w2[0] + w2[1];
    float r = rsqrtf(tot / (float)AA + EPS);
    out[(size_t)j * AA + d] = val * r * lnf[d];
}

// ---------------- launch ----------------
extern "C" void kernel_launch(void* const* d_in, const int* in_sizes, int n_in,
                              void* d_out, int out_size) {
    const float* node_features = (const float*)d_in[0];
    const int*   ids           = (const int*)d_in[1];
    const float* rel           = (const float*)d_in[2];
    const float* We_emb        = (const float*)d_in[3];
    const float* Wq            = (const float*)d_in[4];
    const float* Wk            = (const float*)d_in[5];
    const float* Wv            = (const float*)d_in[6];
    const float* Wedge         = (const float*)d_in[7];
    const float* Wskip         = (const float*)d_in[8];
    const float* Wout          = (const float*)d_in[9];
    const float* lnw           = (const float*)d_in[10];
    const float* Wact          = (const float*)d_in[11];
    const float* lnf           = (const float*)d_in[12];
    float* out = (float*)d_out;

    float *xp, *qp, *tp, *y1p, *wswp, *wqcp, *wkcp, *wvcp, *wocp, *wacp;
    __nv_bfloat16 *kbp, *vbp;
    cudaGetSymbolAddress((void**)&xp, g_x);
    cudaGetSymbolAddress((void**)&qp, g_q);
    cudaGetSymbolAddress((void**)&kbp, g_kb);
    cudaGetSymbolAddress((void**)&vbp, g_vb);
    cudaGetSymbolAddress((void**)&tp, g_t);
    cudaGetSymbolAddress((void**)&y1p, g_y1);
    cudaGetSymbolAddress((void**)&wswp, g_wsw);
    cudaGetSymbolAddress((void**)&wqcp, g_wqc);
    cudaGetSymbolAddress((void**)&wkcp, g_wkc);
    cudaGetSymbolAddress((void**)&wvcp, g_wvc);
    cudaGetSymbolAddress((void**)&wocp, g_woc);
    cudaGetSymbolAddress((void**)&wacp, g_wac);

    static cudaStream_t s1 = nullptr;
    static cudaEvent_t evFork = nullptr, evJoin = nullptr;
    if (!s1) {
        cudaStreamCreateWithFlags(&s1, cudaStreamNonBlocking);
        cudaEventCreateWithFlags(&evFork, cudaEventDisableTiming);
        cudaEventCreateWithFlags(&evJoin, cudaEventDisableTiming);
    }

    dim3 gqkv(HO / 64, NN / 128, 3);
    dim3 gdual(DD / 64, NN / 128, 1);
    dim3 gf(AA / 64, NN / 128, 1);

    cudaEventRecord(evFork, 0);
    cudaStreamWaitEvent(s1, evFork, 0);

    zero_detect_kernel<<<(NN + 255) / 256, 256, 0, s1>>>(ids);
    count_kernel<<<(ENBR + 255) / 256, 256, 0, s1>>>(ids);
    scan_kernel<<<1, 1024, 0, s1>>>();
    scatter_kernel<<<(ENBR + 255) / 256, 256, 0, s1>>>(ids, rel);
    prep_kernel<<<dim3(DD + 4, RR), 128, 0, s1>>>(We_emb, Wedge, Wskip, Wout);
    cudaEventRecord(evJoin, s1);

    conv_kernel<<<(NN * DD + 255) / 256, 256>>>(Wq, Wk, Wv, Wout, Wact, node_features);
    tf32gemm_kernel<<<gqkv, 256>>>(xp, wqcp, wkcp, wvcp,
                                   qp, kbp, vbp, /*bfmask=*/0b110, HO, DD);
    cudaStreamWaitEvent(0, evJoin, 0);

    for (int r = 0; r < RR; r++) {
        if (r > 0) {
            const float* wq = wqcp + (size_t)r * DD * HO;
            const float* wk = wkcp + (size_t)r * DD * HO;
            const float* wv = wvcp + (size_t)r * DD * HO;
            tf32gemm_kernel<<<gqkv, 256>>>(xp, wq, wk, wv,
                                           qp, kbp, vbp, 0b110, HO, DD);
        }
        attn_kernel<<<NN, 128>>>(r);
        tf32gemm_dual_kernel<<<gdual, 256>>>(tp, wocp + (size_t)r * HO * DD,
                                             xp, wswp + (size_t)r * DD * DD,
                                             y1p, DD, HO, DD);
        rmsres_kernel<<<NN, DD>>>(lnw + (size_t)r * DD);
    }

    tf32gemm_kernel<<<gf, 256>>>(xp, wacp, wacp, wacp,
                                 y1p, y1p, y1p, /*bfmask=*/0, AA, DD);
    rmsfinal_kernel<<<NN, AA>>>(y1p, lnf, out);
}

// round 15
// speedup vs baseline: 1.1401x; 1.0232x over previous
#include <cuda_runtime.h>
#include <cuda_bf16.h>
#include <stdint.h>
#include <math.h>

// Problem constants
#define BB 8
#define CC 1024
#define LL 32
#define NN 8192          // B*C
#define DD 128
#define HH 4
#define HO 512           // H*D
#define RR 3
#define AA 64
#define ENBR 262144      // N*L
#define EPS 1e-5f
#define SCALE 0.08838834764831845f   // 1/sqrt(128)

// ---------------- static device scratch ----------------
__device__ __align__(128) float g_x[NN * DD];
__device__ __align__(128) float g_q[NN * HO];
__device__ __align__(128) __nv_bfloat16 g_kb[NN * HO];
__device__ __align__(128) __nv_bfloat16 g_vb[NN * HO];
__device__ __align__(128) float g_t[NN * HO];
__device__ __align__(128) float g_y1[NN * DD];
__device__ __align__(128) float g_y2[NN * DD];
__device__ __align__(128) float g_y3[NN * DD];
__device__ __align__(128) float g_M[RR][2 * HO];
__device__ __align__(128) float g_wsw[RR][DD * DD];
__device__ __align__(128) float g_wqc[RR * DD * HO];
__device__ __align__(128) float g_wkc[RR * DD * HO];
__device__ __align__(128) float g_wvc[RR * DD * HO];
__device__ __align__(128) float g_woc[RR * HO * DD];
__device__ __align__(128) float g_wac[DD * AA];
__device__ int   g_indptr[NN + 1];
__device__ int   g_cnt[NN];
__device__ int   g_cursor[NN];
__device__ int   g_esrc[ENBR];
__device__ __align__(16) float2 g_erel[ENBR];
__device__ int   g_fmt[1];

__device__ __forceinline__ unsigned f2tf32(float x) {
    unsigned r;
    asm("cvt.rna.tf32.f32 %0, %1;" : "=r"(r) : "f"(x));
    return r;
}
__device__ __forceinline__ float tf32r(float x) { return __uint_as_float(f2tf32(x)); }

// ---------------- setup kernels ----------------
__global__ void conv_kernel(const float* __restrict__ Wq, const float* __restrict__ Wk,
                            const float* __restrict__ Wv, const float* __restrict__ Wout,
                            const float* __restrict__ Wact, const float* __restrict__ nf) {
    int i = blockIdx.x * blockDim.x + threadIdx.x;
    const int S = RR * DD * HO;
    if (i < S) {
        g_wqc[i] = tf32r(Wq[i]);
        g_wkc[i] = tf32r(Wk[i]);
        g_wvc[i] = tf32r(Wv[i]);
        g_woc[i] = tf32r(Wout[i]);
        if (i < DD * AA) g_wac[i] = tf32r(Wact[i]);
    }
    if (i < NN * DD) g_x[i] = tf32r(nf[i]);
}

__global__ void zero_detect_kernel(const int* __restrict__ ids) {
    int i = blockIdx.x * blockDim.x + threadIdx.x;
    if (i < NN) g_cnt[i] = 0;
    if (blockIdx.x == 0 && threadIdx.x < 32) {
        int nz = 0;
        for (int k2 = threadIdx.x; k2 < 64; k2 += 32)
            nz |= (ids[2 * k2 + 1] != 0);
        nz = __any_sync(0xffffffffu, nz);
        if (threadIdx.x == 0) g_fmt[0] = nz ? 0 : 1;
    }
}

__device__ __forceinline__ int load_id(const int* __restrict__ ids, int idx, int fmt64) {
    return fmt64 ? ids[2 * idx] : ids[idx];
}

__global__ void count_kernel(const int* __restrict__ ids) {
    int idx = blockIdx.x * blockDim.x + threadIdx.x;
    if (idx >= ENBR) return;
    int fmt = g_fmt[0];
    int id = load_id(ids, idx, fmt);
    int n = idx >> 5;
    int dst = (n & ~(CC - 1)) | id;
    atomicAdd(&g_cnt[dst], 1);
}

// warp-shuffle scan
__global__ void scan_kernel() {
    __shared__ int wsum[32];
    int t = threadIdx.x;
    int lane = t & 31, wid = t >> 5;
    int local[8];
    int s = 0;
#pragma unroll
    for (int i = 0; i < 8; i++) { local[i] = g_cnt[t * 8 + i]; s += local[i]; }
    int v = s;
#pragma unroll
    for (int off = 1; off < 32; off <<= 1) {
        int u = __shfl_up_sync(0xffffffffu, v, off);
        if (lane >= off) v += u;
    }
    if (lane == 31) wsum[wid] = v;
    __syncthreads();
    if (wid == 0) {
        int wv = wsum[lane];
#pragma unroll
        for (int off = 1; off < 32; off <<= 1) {
            int u = __shfl_up_sync(0xffffffffu, wv, off);
            if (lane >= off) wv += u;
        }
        wsum[lane] = wv;
    }
    __syncthreads();
    int base = (wid ? wsum[wid - 1] : 0) + v - s;
#pragma unroll
    for (int i = 0; i < 8; i++) {
        g_indptr[t * 8 + i] = base;
        g_cursor[t * 8 + i] = base;
        base += local[i];
    }
    if (t == 1023) g_indptr[NN] = base;
}

__global__ void scatter_kernel(const int* __restrict__ ids, const float* __restrict__ rc) {
    int idx = blockIdx.x * blockDim.x + threadIdx.x;
    if (idx >= ENBR) return;
    int fmt = g_fmt[0];
    int id = load_id(ids, idx, fmt);
    int n = idx >> 5;
    int l = idx & 31;
    int dst = (n & ~(CC - 1)) | id;
    int pos = atomicAdd(&g_cursor[dst], 1);
    g_esrc[pos] = n;
    g_erel[pos] = make_float2(rc[n * (2 * LL) + 2 * l], rc[n * (2 * LL) + 2 * l + 1]);
}

__global__ __launch_bounds__(128) void prep_kernel(
    const float* __restrict__ We, const float* __restrict__ Wedge,
    const float* __restrict__ Wskip, const float* __restrict__ Wout)
{
    int r = blockIdx.y;
    const float* Wer = We + (size_t)r * 2 * DD;
    const float* Wedger = Wedge + (size_t)r * DD * HO;
    const float* Wskipr = Wskip + (size_t)r * DD * HO;
    const float* Woutr = Wout + (size_t)r * HO * DD;
    int b = blockIdx.x;
    if (b < DD) {
        __shared__ float row[HO];
        for (int i = threadIdx.x; i < HO; i += 128) row[i] = Wskipr[b * HO + i];
        __syncthreads();
        float s = 0.f;
        for (int k2 = 0; k2 < HO; k2++) s += row[k2] * Woutr[k2 * DD + threadIdx.x];
        g_wsw[r][b * DD + threadIdx.x] = tf32r(s);
    } else {
        int o = (b - DD) * 128 + threadIdx.x;
        float s0 = 0.f, s1 = 0.f;
        for (int d = 0; d < DD; d++) {
            float w = Wedger[d * HO + o];
            s0 += Wer[d] * w;
            s1 += Wer[DD + d] * w;
        }
        g_M[r][o] = s0;
        g_M[r][HO + o] = s1;
    }
}

// ---------------- tf32 GEMM core (cp.async + ldmatrix) ----------------
__device__ __forceinline__ void mma_tf32(float* c, unsigned a0, unsigned a1, unsigned a2,
                                         unsigned a3, unsigned b0, unsigned b1) {
    asm volatile(
        "mma.sync.aligned.m16n8k8.row.col.f32.tf32.tf32.f32 "
        "{%0,%1,%2,%3}, {%4,%5,%6,%7}, {%8,%9}, {%0,%1,%2,%3};"
        : "+f"(c[0]), "+f"(c[1]), "+f"(c[2]), "+f"(c[3])
        : "r"(a0), "r"(a1), "r"(a2), "r"(a3), "r"(b0), "r"(b1));
}

__device__ __forceinline__ void ldm4(unsigned* r, unsigned addr) {
    asm volatile("ldmatrix.sync.aligned.m8n8.x4.shared.b16 {%0,%1,%2,%3}, [%4];"
                 : "=r"(r[0]), "=r"(r[1]), "=r"(r[2]), "=r"(r[3]) : "r"(addr));
}

// A row stride (lda) decoupled from K extent (kd) so K-slices of a wider matrix work.
__device__ __forceinline__ void gemm_phase(
    const float* __restrict__ Ap, const float* __restrict__ Bp, int kd, int lda, int Ndim,
    unsigned sbase, int tid, int bm, int bn,
    unsigned a_l, unsigned b_l, float acc[2][4][4])
{
    const int arow = tid >> 2, akq = tid & 3;
    const float* asrc = Ap + (size_t)(bm + arow) * lda + akq * 4;
    const size_t asrc2 = (size_t)64 * lda;
    const unsigned adst = sbase + arow * 80 + akq * 16;

    const int bnn = tid & 63, bk4 = (tid >> 6) * 4;
    const float* bsrc = Bp + (size_t)bk4 * Ndim + bn + bnn;
    const unsigned bdst = sbase + 30720 + bnn * 80 + bk4 * 4;
    float br0, br1, br2, br3;
    const int nch = kd >> 4;

#define CPA(c, bufA) do {                                                        \
    const float* s0_ = asrc + (c) * 16;                                          \
    unsigned d0_ = adst + (bufA) * 10240;                                        \
    asm volatile("cp.async.cg.shared.global [%0],[%1],16;\n"                     \
                 "cp.async.cg.shared.global [%2],[%3],16;\n"                     \
                 "cp.async.commit_group;\n"                                      \
                 :: "r"(d0_), "l"(s0_), "r"(d0_ + 64 * 80), "l"(s0_ + asrc2));   \
} while (0)
#define LDGB(c) do {                                                             \
    const float* p_ = bsrc + (size_t)(c) * 16 * Ndim;                            \
    br0 = __ldg(p_); br1 = __ldg(p_ + Ndim);                                     \
    br2 = __ldg(p_ + 2 * (size_t)Ndim); br3 = __ldg(p_ + 3 * (size_t)Ndim);      \
} while (0)
#define STSB(bufB)                                                               \
    asm volatile("st.shared.v4.f32 [%0], {%1,%2,%3,%4};"                         \
                 :: "r"(bdst + (bufB) * 5120), "f"(br0), "f"(br1), "f"(br2), "f"(br3))

    CPA(0, 0);
    CPA(1, 1);
    LDGB(0);
    STSB(0);
    LDGB(1);
    asm volatile("cp.async.wait_group 1;" ::: "memory");
    __syncthreads();

    int bufA = 0;
    for (int c = 0; c < nch; c++) {
        int bufB = c & 1;
        if (c + 2 < nch) {
            int tb = bufA + 2; if (tb >= 3) tb -= 3;
            CPA(c + 2, tb);
        }
        const unsigned abase = a_l + bufA * 10240;
        const unsigned bbase = b_l + bufB * 5120;
#pragma unroll
        for (int kk = 0; kk < 2; kk++) {
            unsigned a[2][4], b[2][4];
            ldm4(a[0], abase + kk * 32);
            ldm4(a[1], abase + 1280 + kk * 32);
            ldm4(b[0], bbase + kk * 32);
            ldm4(b[1], bbase + 1280 + kk * 32);
#pragma unroll
            for (int i = 0; i < 2; i++) {
                mma_tf32(acc[i][0], a[i][0], a[i][1], a[i][2], a[i][3], b[0][0], b[0][1]);
                mma_tf32(acc[i][1], a[i][0], a[i][1], a[i][2], a[i][3], b[0][2], b[0][3]);
                mma_tf32(acc[i][2], a[i][0], a[i][1], a[i][2], a[i][3], b[1][0], b[1][1]);
                mma_tf32(acc[i][3], a[i][0], a[i][1], a[i][2], a[i][3], b[1][2], b[1][3]);
            }
        }
        if (c < nch - 1) {
            STSB(bufB ^ 1);
            if (c + 2 < nch) {
                LDGB(c + 2);
                asm volatile("cp.async.wait_group 1;" ::: "memory");
            } else {
                asm volatile("cp.async.wait_group 0;" ::: "memory");
            }
            __syncthreads();
        }
        if (++bufA == 3) bufA = 0;
    }
#undef CPA
#undef LDGB
#undef STSB
}

// z-sliced GEMM: per-slice A, B, C, K, lda
__global__ __launch_bounds__(256) void tf32gemm_kernel(
    const float* __restrict__ A0, const float* __restrict__ A1,
    const float* __restrict__ A2,
    const float* __restrict__ B0, const float* __restrict__ B1,
    const float* __restrict__ B2,
    void* __restrict__ C0, void* __restrict__ C1, void* __restrict__ C2,
    int bfmask, int Ndim, int4 Kdims, int4 Ldas)
{
    const float* Ap;
    const float* Bp;
    void* Cp;
    int kd, lda;
    switch (blockIdx.z) {
        case 0: Ap = A0; Bp = B0; Cp = C0; kd = Kdims.x; lda = Ldas.x; break;
        case 1: Ap = A1; Bp = B1; Cp = C1; kd = Kdims.y; lda = Ldas.y; break;
        default: Ap = A2; Bp = B2; Cp = C2; kd = Kdims.z; lda = Ldas.z; break;
    }
    const bool bf16out = (bfmask >> blockIdx.z) & 1;

    __shared__ __align__(16) char smem_raw[40960];
    const unsigned sbase = (unsigned)__cvta_generic_to_shared(smem_raw);

    const int tid = threadIdx.x;
    const int bm = blockIdx.y * 128, bn = blockIdx.x * 64;
    const int lane = tid & 31;
    const int w = tid >> 5;
    const int wm = w & 3, wn = w >> 2;
    const int lq = lane >> 2, lr = lane & 3;

    const unsigned a_l = sbase + (wm * 32 + (lane & 15)) * 80 + (lane >> 4) * 16;
    const unsigned b_l = sbase + 30720 +
        (wn * 32 + (lane & 7) + ((lane >> 4) & 1) * 8) * 80 + ((lane >> 3) & 1) * 16;

    float acc[2][4][4];
#pragma unroll
    for (int i = 0; i < 2; i++)
#pragma unroll
        for (int j = 0; j < 4; j++)
#pragma unroll
            for (int u = 0; u < 4; u++) acc[i][j][u] = 0.f;

    gemm_phase(Ap, Bp, kd, lda, Ndim, sbase, tid, bm, bn, a_l, b_l, acc);

#pragma unroll
    for (int i = 0; i < 2; i++) {
#pragma unroll
        for (int j = 0; j < 4; j++) {
            int row = bm + wm * 32 + i * 16 + lq;
            int col = bn + wn * 32 + j * 8 + lr * 2;
            if (bf16out) {
                __nv_bfloat16* Cb = (__nv_bfloat16*)Cp;
                *(__nv_bfloat162*)(Cb + (size_t)row * Ndim + col) =
                    __float22bfloat162_rn(make_float2(acc[i][j][0], acc[i][j][1]));
                *(__nv_bfloat162*)(Cb + (size_t)(row + 8) * Ndim + col) =
                    __float22bfloat162_rn(make_float2(acc[i][j][2], acc[i][j][3]));
            } else {
                float* Cf = (float*)Cp;
                *(float2*)(Cf + (size_t)row * Ndim + col) =
                    make_float2(acc[i][j][0], acc[i][j][1]);
                *(float2*)(Cf + (size_t)(row + 8) * Ndim + col) =
                    make_float2(acc[i][j][2], acc[i][j][3]);
            }
        }
    }
}

// ---------------- attention: warp = edge-quarter, lanes cover all 4 heads ----------------
__device__ __forceinline__ float2 bf2f(unsigned u) {
    __nv_bfloat162 h = *reinterpret_cast<__nv_bfloat162*>(&u);
    return __bfloat1622float2(h);
}

__device__ __forceinline__ float dot16(const float* q, uint4 a, uint4 b) {
    float s = 0.f;
    const unsigned* wa = (const unsigned*)&a;
#pragma unroll
    for (int i = 0; i < 4; i++) {
        float2 f = bf2f(wa[i]);
        s += q[2 * i] * f.x + q[2 * i + 1] * f.y;
    }
    const unsigned* wb = (const unsigned*)&b;
#pragma unroll
    for (int i = 0; i < 4; i++) {
        float2 f = bf2f(wb[i]);
        s += q[8 + 2 * i] * f.x + q[9 + 2 * i] * f.y;
    }
    return s;
}

__device__ __forceinline__ void axpy16(float* acc, float fold, float w, uint4 a, uint4 b) {
    const unsigned* wa = (const unsigned*)&a;
#pragma unroll
    for (int i = 0; i < 4; i++) {
        float2 f = bf2f(wa[i]);
        acc[2 * i]     = acc[2 * i] * fold + w * f.x;
        acc[2 * i + 1] = acc[2 * i + 1] * fold + w * f.y;
    }
    const unsigned* wb = (const unsigned*)&b;
#pragma unroll
    for (int i = 0; i < 4; i++) {
        float2 f = bf2f(wb[i]);
        acc[8 + 2 * i] = acc[8 + 2 * i] * fold + w * f.x;
        acc[9 + 2 * i] = acc[9 + 2 * i] * fold + w * f.y;
    }
}

__global__ __launch_bounds__(128) void attn_kernel(int r) {
    const int j = blockIdx.x;
    const int tid = threadIdx.x;
    const int warp = tid >> 5, lane = tid & 31;
    const int h = lane >> 3, sub = lane & 7;
    const int hd0 = h * DD + sub * 16;
    const size_t jbase = (size_t)j * HO + hd0;

    float qr[16];
    {
        const float4* qp4 = (const float4*)(g_q + jbase);
#pragma unroll
        for (int i = 0; i < 4; i++) {
            float4 v = qp4[i];
            qr[i * 4 + 0] = v.x; qr[i * 4 + 1] = v.y;
            qr[i * 4 + 2] = v.z; qr[i * 4 + 3] = v.w;
        }
    }
    float qMx = 0.f, qMy = 0.f;
    {
        const float* mx = g_M[r] + hd0;
        const float* my = g_M[r] + HO + hd0;
#pragma unroll
        for (int i = 0; i < 16; i++) { qMx += qr[i] * mx[i]; qMy += qr[i] * my[i]; }
#pragma unroll
        for (int o = 1; o < 8; o <<= 1) {
            qMx += __shfl_xor_sync(0xffffffffu, qMx, o);
            qMy += __shfl_xor_sync(0xffffffffu, qMy, o);
        }
    }

    float m = -1e30f, den = 0.f, cx = 0.f, cy = 0.f;
    float acc[16];
#pragma unroll
    for (int i = 0; i < 16; i++) acc[i] = 0.f;

    if (warp == 0) {
        uint4 k0 = *(const uint4*)(g_kb + jbase);
        uint4 k1 = *(const uint4*)(g_kb + jbase + 8);
        uint4 v0 = *(const uint4*)(g_vb + jbase);
        uint4 v1 = *(const uint4*)(g_vb + jbase + 8);
        float part = dot16(qr, k0, k1);
#pragma unroll
        for (int o = 1; o < 8; o <<= 1) part += __shfl_xor_sync(0xffffffffu, part, o);
        m = part * SCALE;
        den = 1.f;
        axpy16(acc, 0.f, 1.f, v0, v1);
    }

    const int e0 = g_indptr[j], e1 = g_indptr[j + 1];
    for (int ei = e0 + warp; ei < e1; ei += 4) {
        int s = g_esrc[ei];
        float2 rr = g_erel[ei];
        const size_t sb = (size_t)s * HO + hd0;
        uint4 k0 = *(const uint4*)(g_kb + sb);
        uint4 k1 = *(const uint4*)(g_kb + sb + 8);
        uint4 v0 = *(const uint4*)(g_vb + sb);
        uint4 v1 = *(const uint4*)(g_vb + sb + 8);
        float part = dot16(qr, k0, k1) + (rr.x * qMx + rr.y * qMy) * 0.125f;
#pragma unroll
        for (int o = 1; o < 8; o <<= 1) part += __shfl_xor_sync(0xffffffffu, part, o);
        float alpha = part * SCALE;
        float mn = fmaxf(m, alpha);
        float fold = __expf(m - mn);
        float w = __expf(alpha - mn);
        den = den * fold + w;
        cx = cx * fold + w * rr.x;
        cy = cy * fold + w * rr.y;
        axpy16(acc, fold, w, v0, v1);
        m = mn;
    }

    __shared__ float s_m[4][4], s_den[4][4], s_cx[4][4], s_cy[4][4];
    __shared__ float s_acc[4][HO];
    if (sub == 0) {
        s_m[warp][h] = m; s_den[warp][h] = den;
        s_cx[warp][h] = cx; s_cy[warp][h] = cy;
    }
#pragma unroll
    for (int i = 0; i < 4; i++)
        *(float4*)&s_acc[warp][hd0 + i * 4] =
            make_float4(acc[i * 4], acc[i * 4 + 1], acc[i * 4 + 2], acc[i * 4 + 3]);
    __syncthreads();

    const int d = tid * 4;
    const int hh = tid >> 5;
    float M = fmaxf(fmaxf(s_m[0][hh], s_m[1][hh]), fmaxf(s_m[2][hh], s_m[3][hh]));
    float f0 = __expf(s_m[0][hh] - M), f1 = __expf(s_m[1][hh] - M);
    float f2 = __expf(s_m[2][hh] - M), f3 = __expf(s_m[3][hh] - M);
    float dtot = s_den[0][hh] * f0 + s_den[1][hh] * f1 + s_den[2][hh] * f2 + s_den[3][hh] * f3;
    float cxT = s_cx[0][hh] * f0 + s_cx[1][hh] * f1 + s_cx[2][hh] * f2 + s_cx[3][hh] * f3;
    float cyT = s_cy[0][hh] * f0 + s_cy[1][hh] * f1 + s_cy[2][hh] * f2 + s_cy[3][hh] * f3;
    float inv = 1.f / dtot;
    const float* mx = g_M[r] + d;
    const float* my = g_M[r] + HO + d;
    float o4[4];
#pragma unroll
    for (int i = 0; i < 4; i++) {
        float a = s_acc[0][d + i] * f0 + s_acc[1][d + i] * f1 +
                  s_acc[2][d + i] * f2 + s_acc[3][d + i] * f3;
        o4[i] = tf32r((a + cxT * mx[i] + cyT * my[i]) * inv);
    }
    *(float4*)(g_t + (size_t)j * HO + d) = make_float4(o4[0], o4[1], o4[2], o4[3]);
}

// x_out = tf32(rmsnorm(y1 + y2 + y3 + x_in, ln_w))
__global__ __launch_bounds__(128) void rmsres_kernel(const float* __restrict__ lnw) {
    int j = blockIdx.x, d = threadIdx.x;
    size_t i = (size_t)j * DD + d;
    float val = g_y1[i] + g_y2[i] + g_y3[i] + g_x[i];
    float ss = val * val;
#pragma unroll
    for (int off = 16; off; off >>= 1) ss += __shfl_xor_sync(0xffffffffu, ss, off);
    __shared__ float w4[4];
    if ((threadIdx.x & 31) == 0) w4[threadIdx.x >> 5] = ss;
    __syncthreads();
    float tot = w4[0] + w4[1] + w4[2] + w4[3];
    float r = rsqrtf(tot / (float)DD + EPS);
    g_x[i] = tf32r(val * r * lnw[d]);
}

// out = rmsnorm(y, ln_f)
__global__ __launch_bounds__(64) void rmsfinal_kernel(const float* __restrict__ y,
                                                      const float* __restrict__ lnf,
                                                      float* __restrict__ out) {
    int j = blockIdx.x, d = threadIdx.x;
    float val = y[(size_t)j * AA + d];
    float ss = val * val;
#pragma unroll
    for (int off = 16; off; off >>= 1) ss += __shfl_xor_sync(0xffffffffu, ss, off);
    __shared__ float w2[2];
    if ((threadIdx.x & 31) == 0) w2[threadIdx.x >> 5] = ss;
    __syncthreads();
    float tot = w2[0] + w2[1];
    float r = rsqrtf(tot / (float)AA + EPS);
    out[(size_t)j * AA + d] = val * r * lnf[d];
}

// ---------------- launch ----------------
extern "C" void kernel_launch(void* const* d_in, const int* in_sizes, int n_in,
                              void* d_out, int out_size) {
    const float* node_features = (const float*)d_in[0];
    const int*   ids           = (const int*)d_in[1];
    const float* rel           = (const float*)d_in[2];
    const float* We_emb        = (const float*)d_in[3];
    const float* Wq            = (const float*)d_in[4];
    const float* Wk            = (const float*)d_in[5];
    const float* Wv            = (const float*)d_in[6];
    const float* Wedge         = (const float*)d_in[7];
    const float* Wskip         = (const float*)d_in[8];
    const float* Wout          = (const float*)d_in[9];
    const float* lnw           = (const float*)d_in[10];
    const float* Wact          = (const float*)d_in[11];
    const float* lnf           = (const float*)d_in[12];
    float* out = (float*)d_out;

    float *xp, *qp, *tp, *y1p, *y2p, *y3p, *wswp, *wqcp, *wkcp, *wvcp, *wocp, *wacp;
    __nv_bfloat16 *kbp, *vbp;
    cudaGetSymbolAddress((void**)&xp, g_x);
    cudaGetSymbolAddress((void**)&qp, g_q);
    cudaGetSymbolAddress((void**)&kbp, g_kb);
    cudaGetSymbolAddress((void**)&vbp, g_vb);
    cudaGetSymbolAddress((void**)&tp, g_t);
    cudaGetSymbolAddress((void**)&y1p, g_y1);
    cudaGetSymbolAddress((void**)&y2p, g_y2);
    cudaGetSymbolAddress((void**)&y3p, g_y3);
    cudaGetSymbolAddress((void**)&wswp, g_wsw);
    cudaGetSymbolAddress((void**)&wqcp, g_wqc);
    cudaGetSymbolAddress((void**)&wkcp, g_wkc);
    cudaGetSymbolAddress((void**)&wvcp, g_wvc);
    cudaGetSymbolAddress((void**)&wocp, g_woc);
    cudaGetSymbolAddress((void**)&wacp, g_wac);

    static cudaStream_t s1 = nullptr;
    static cudaEvent_t evFork = nullptr, evJoin = nullptr;
    if (!s1) {
        cudaStreamCreateWithFlags(&s1, cudaStreamNonBlocking);
        cudaEventCreateWithFlags(&evFork, cudaEventDisableTiming);
        cudaEventCreateWithFlags(&evJoin, cudaEventDisableTiming);
    }

    dim3 gqkv(HO / 64, NN / 128, 3);
    dim3 gy(DD / 64, NN / 128, 3);
    dim3 gf(AA / 64, NN / 128, 1);

    cudaEventRecord(evFork, 0);
    cudaStreamWaitEvent(s1, evFork, 0);

    zero_detect_kernel<<<(NN + 255) / 256, 256, 0, s1>>>(ids);
    count_kernel<<<(ENBR + 255) / 256, 256, 0, s1>>>(ids);
    scan_kernel<<<1, 1024, 0, s1>>>();
    scatter_kernel<<<(ENBR + 255) / 256, 256, 0, s1>>>(ids, rel);
    prep_kernel<<<dim3(DD + 4, RR), 128, 0, s1>>>(We_emb, Wedge, Wskip, Wout);
    cudaEventRecord(evJoin, s1);

    conv_kernel<<<(NN * DD + 255) / 256, 256>>>(Wq, Wk, Wv, Wout, Wact, node_features);
    tf32gemm_kernel<<<gqkv, 256>>>(xp, xp, xp, wqcp, wkcp, wvcp,
                                   qp, kbp, vbp, /*bfmask=*/0b110, HO,
                                   make_int4(DD, DD, DD, 0),
                                   make_int4(DD, DD, DD, 0));
    cudaStreamWaitEvent(0, evJoin, 0);

    for (int r = 0; r < RR; r++) {
        if (r > 0) {
            const float* wq = wqcp + (size_t)r * DD * HO;
            const float* wk = wkcp + (size_t)r * DD * HO;
            const float* wv = wvcp + (size_t)r * DD * HO;
            tf32gemm_kernel<<<gqkv, 256>>>(xp, xp, xp, wq, wk, wv,
                                           qp, kbp, vbp, 0b110, HO,
                                           make_int4(DD, DD, DD, 0),
                                           make_int4(DD, DD, DD, 0));
        }
        attn_kernel<<<NN, 128>>>(r);
        // y1 = t[:,0:256]@Wout[0:256]  (K=256, lda=HO)
        // y2 = t[:,256:512]@Wout[256:512]
        // y3 = x@Wsw (K=128, lda=DD)
        const float* wo = wocp + (size_t)r * HO * DD;
        tf32gemm_kernel<<<gy, 256>>>(tp, tp + 256, xp,
                                     wo, wo + 256 * DD,
                                     wswp + (size_t)r * DD * DD,
                                     y1p, y2p, y3p, /*bfmask=*/0, DD,
                                     make_int4(256, 256, DD, 0),
                                     make_int4(HO, HO, DD, 0));
        rmsres_kernel<<<NN, DD>>>(lnw + (size_t)r * DD);
    }

    tf32gemm_kernel<<<gf, 256>>>(xp, xp, xp, wacp, wacp, wacp,
                                 y1p, y1p, y1p, /*bfmask=*/0, AA,
                                 make_int4(DD, DD, DD, 0),
                                 make_int4(DD, DD, DD, 0));
    rmsfinal_kernel<<<NN, AA>>>(y1p, lnf, out);
}

// round 16
// speedup vs baseline: 1.1591x; 1.0166x over previous
#include <cuda_runtime.h>
#include <cuda_bf16.h>
#include <stdint.h>
#include <math.h>

// Problem constants
#define BB 8
#define CC 1024
#define LL 32
#define NN 8192          // B*C
#define DD 128
#define HH 4
#define HO 512           // H*D
#define RR 3
#define AA 64
#define ENBR 262144      // N*L
#define EPS 1e-5f
#define SCALE 0.08838834764831845f   // 1/sqrt(128)

// ---------------- static device scratch ----------------
__device__ __align__(128) float g_x[NN * DD];
__device__ __align__(128) float g_q[NN * HO];
__device__ __align__(128) __nv_bfloat16 g_kb[NN * HO];
__device__ __align__(128) __nv_bfloat16 g_vb[NN * HO];
__device__ __align__(128) float g_t[NN * HO];
__device__ __align__(128) float g_y1[NN * DD];
__device__ __align__(128) float g_y2[NN * DD];
__device__ __align__(128) float g_y3[NN * DD];
__device__ __align__(128) float g_M[RR][2 * HO];
__device__ __align__(128) float g_wsw[RR][DD * DD];
__device__ __align__(128) float g_wqc[RR * DD * HO];
__device__ __align__(128) float g_wkc[RR * DD * HO];
__device__ __align__(128) float g_wvc[RR * DD * HO];
__device__ __align__(128) float g_woc[RR * HO * DD];
__device__ __align__(128) float g_wac[DD * AA];
__device__ int   g_indptr[NN + 1];
__device__ int   g_cnt[NN];
__device__ int   g_cursor[NN];
__device__ int   g_esrc[ENBR];
__device__ __align__(16) float2 g_erel[ENBR];
__device__ int   g_fmt[1];

__device__ __forceinline__ unsigned f2tf32(float x) {
    unsigned r;
    asm("cvt.rna.tf32.f32 %0, %1;" : "=r"(r) : "f"(x));
    return r;
}
__device__ __forceinline__ float tf32r(float x) { return __uint_as_float(f2tf32(x)); }

// ---------------- setup kernels ----------------
__global__ void conv_kernel(const float* __restrict__ Wq, const float* __restrict__ Wk,
                            const float* __restrict__ Wv, const float* __restrict__ Wout,
                            const float* __restrict__ Wact, const float* __restrict__ nf) {
    int i = blockIdx.x * blockDim.x + threadIdx.x;
    const int S = RR * DD * HO;
    if (i < S) {
        g_wqc[i] = tf32r(Wq[i]);
        g_wkc[i] = tf32r(Wk[i]);
        g_wvc[i] = tf32r(Wv[i]);
        g_woc[i] = tf32r(Wout[i]);
        if (i < DD * AA) g_wac[i] = tf32r(Wact[i]);
    }
    if (i < NN * DD) g_x[i] = tf32r(nf[i]);
}

__global__ void zero_detect_kernel(const int* __restrict__ ids) {
    int i = blockIdx.x * blockDim.x + threadIdx.x;
    if (i < NN) g_cnt[i] = 0;
    if (blockIdx.x == 0 && threadIdx.x < 32) {
        int nz = 0;
        for (int k2 = threadIdx.x; k2 < 64; k2 += 32)
            nz |= (ids[2 * k2 + 1] != 0);
        nz = __any_sync(0xffffffffu, nz);
        if (threadIdx.x == 0) g_fmt[0] = nz ? 0 : 1;
    }
}

__device__ __forceinline__ int load_id(const int* __restrict__ ids, int idx, int fmt64) {
    return fmt64 ? ids[2 * idx] : ids[idx];
}

__global__ void count_kernel(const int* __restrict__ ids) {
    int idx = blockIdx.x * blockDim.x + threadIdx.x;
    if (idx >= ENBR) return;
    int fmt = g_fmt[0];
    int id = load_id(ids, idx, fmt);
    int n = idx >> 5;
    int dst = (n & ~(CC - 1)) | id;
    atomicAdd(&g_cnt[dst], 1);
}

// warp-shuffle scan
__global__ void scan_kernel() {
    __shared__ int wsum[32];
    int t = threadIdx.x;
    int lane = t & 31, wid = t >> 5;
    int local[8];
    int s = 0;
#pragma unroll
    for (int i = 0; i < 8; i++) { local[i] = g_cnt[t * 8 + i]; s += local[i]; }
    int v = s;
#pragma unroll
    for (int off = 1; off < 32; off <<= 1) {
        int u = __shfl_up_sync(0xffffffffu, v, off);
        if (lane >= off) v += u;
    }
    if (lane == 31) wsum[wid] = v;
    __syncthreads();
    if (wid == 0) {
        int wv = wsum[lane];
#pragma unroll
        for (int off = 1; off < 32; off <<= 1) {
            int u = __shfl_up_sync(0xffffffffu, wv, off);
            if (lane >= off) wv += u;
        }
        wsum[lane] = wv;
    }
    __syncthreads();
    int base = (wid ? wsum[wid - 1] : 0) + v - s;
#pragma unroll
    for (int i = 0; i < 8; i++) {
        g_indptr[t * 8 + i] = base;
        g_cursor[t * 8 + i] = base;
        base += local[i];
    }
    if (t == 1023) g_indptr[NN] = base;
}

__global__ void scatter_kernel(const int* __restrict__ ids, const float* __restrict__ rc) {
    int idx = blockIdx.x * blockDim.x + threadIdx.x;
    if (idx >= ENBR) return;
    int fmt = g_fmt[0];
    int id = load_id(ids, idx, fmt);
    int n = idx >> 5;
    int l = idx & 31;
    int dst = (n & ~(CC - 1)) | id;
    int pos = atomicAdd(&g_cursor[dst], 1);
    g_esrc[pos] = n;
    g_erel[pos] = make_float2(rc[n * (2 * LL) + 2 * l], rc[n * (2 * LL) + 2 * l + 1]);
}

__global__ __launch_bounds__(128) void prep_kernel(
    const float* __restrict__ We, const float* __restrict__ Wedge,
    const float* __restrict__ Wskip, const float* __restrict__ Wout)
{
    int r = blockIdx.y;
    const float* Wer = We + (size_t)r * 2 * DD;
    const float* Wedger = Wedge + (size_t)r * DD * HO;
    const float* Wskipr = Wskip + (size_t)r * DD * HO;
    const float* Woutr = Wout + (size_t)r * HO * DD;
    int b = blockIdx.x;
    if (b < DD) {
        __shared__ float row[HO];
        for (int i = threadIdx.x; i < HO; i += 128) row[i] = Wskipr[b * HO + i];
        __syncthreads();
        float s = 0.f;
        for (int k2 = 0; k2 < HO; k2++) s += row[k2] * Woutr[k2 * DD + threadIdx.x];
        g_wsw[r][b * DD + threadIdx.x] = tf32r(s);
    } else {
        int o = (b - DD) * 128 + threadIdx.x;
        float s0 = 0.f, s1 = 0.f;
        for (int d = 0; d < DD; d++) {
            float w = Wedger[d * HO + o];
            s0 += Wer[d] * w;
            s1 += Wer[DD + d] * w;
        }
        g_M[r][o] = s0;
        g_M[r][HO + o] = s1;
    }
}

// ---------------- tf32 GEMM core (cp.async + ldmatrix) ----------------
__device__ __forceinline__ void mma_tf32(float* c, unsigned a0, unsigned a1, unsigned a2,
                                         unsigned a3, unsigned b0, unsigned b1) {
    asm volatile(
        "mma.sync.aligned.m16n8k8.row.col.f32.tf32.tf32.f32 "
        "{%0,%1,%2,%3}, {%4,%5,%6,%7}, {%8,%9}, {%0,%1,%2,%3};"
        : "+f"(c[0]), "+f"(c[1]), "+f"(c[2]), "+f"(c[3])
        : "r"(a0), "r"(a1), "r"(a2), "r"(a3), "r"(b0), "r"(b1));
}

__device__ __forceinline__ void ldm4(unsigned* r, unsigned addr) {
    asm volatile("ldmatrix.sync.aligned.m8n8.x4.shared.b16 {%0,%1,%2,%3}, [%4];"
                 : "=r"(r[0]), "=r"(r[1]), "=r"(r[2]), "=r"(r[3]) : "r"(addr));
}

__device__ __forceinline__ void gemm_phase(
    const float* __restrict__ Ap, const float* __restrict__ Bp, int kd, int lda, int Ndim,
    unsigned sbase, int tid, int bm, int bn,
    unsigned a_l, unsigned b_l, float acc[2][4][4])
{
    const int arow = tid >> 2, akq = tid & 3;
    const float* asrc = Ap + (size_t)(bm + arow) * lda + akq * 4;
    const size_t asrc2 = (size_t)64 * lda;
    const unsigned adst = sbase + arow * 80 + akq * 16;

    const int bnn = tid & 63, bk4 = (tid >> 6) * 4;
    const float* bsrc = Bp + (size_t)bk4 * Ndim + bn + bnn;
    const unsigned bdst = sbase + 30720 + bnn * 80 + bk4 * 4;
    float br0, br1, br2, br3;
    const int nch = kd >> 4;

#define CPA(c, bufA) do {                                                        \
    const float* s0_ = asrc + (c) * 16;                                          \
    unsigned d0_ = adst + (bufA) * 10240;                                        \
    asm volatile("cp.async.cg.shared.global [%0],[%1],16;\n"                     \
                 "cp.async.cg.shared.global [%2],[%3],16;\n"                     \
                 "cp.async.commit_group;\n"                                      \
                 :: "r"(d0_), "l"(s0_), "r"(d0_ + 64 * 80), "l"(s0_ + asrc2));   \
} while (0)
#define LDGB(c) do {                                                             \
    const float* p_ = bsrc + (size_t)(c) * 16 * Ndim;                            \
    br0 = __ldg(p_); br1 = __ldg(p_ + Ndim);                                     \
    br2 = __ldg(p_ + 2 * (size_t)Ndim); br3 = __ldg(p_ + 3 * (size_t)Ndim);      \
} while (0)
#define STSB(bufB)                                                               \
    asm volatile("st.shared.v4.f32 [%0], {%1,%2,%3,%4};"                         \
                 :: "r"(bdst + (bufB) * 5120), "f"(br0), "f"(br1), "f"(br2), "f"(br3))

    CPA(0, 0);
    CPA(1, 1);
    LDGB(0);
    STSB(0);
    LDGB(1);
    asm volatile("cp.async.wait_group 1;" ::: "memory");
    __syncthreads();

    int bufA = 0;
    for (int c = 0; c < nch; c++) {
        int bufB = c & 1;
        if (c + 2 < nch) {
            int tb = bufA + 2; if (tb >= 3) tb -= 3;
            CPA(c + 2, tb);
        }
        const unsigned abase = a_l + bufA * 10240;
        const unsigned bbase = b_l + bufB * 5120;
#pragma unroll
        for (int kk = 0; kk < 2; kk++) {
            unsigned a[2][4], b[2][4];
            ldm4(a[0], abase + kk * 32);
            ldm4(a[1], abase + 1280 + kk * 32);
            ldm4(b[0], bbase + kk * 32);
            ldm4(b[1], bbase + 1280 + kk * 32);
#pragma unroll
            for (int i = 0; i < 2; i++) {
                mma_tf32(acc[i][0], a[i][0], a[i][1], a[i][2], a[i][3], b[0][0], b[0][1]);
                mma_tf32(acc[i][1], a[i][0], a[i][1], a[i][2], a[i][3], b[0][2], b[0][3]);
                mma_tf32(acc[i][2], a[i][0], a[i][1], a[i][2], a[i][3], b[1][0], b[1][1]);
                mma_tf32(acc[i][3], a[i][0], a[i][1], a[i][2], a[i][3], b[1][2], b[1][3]);
            }
        }
        if (c < nch - 1) {
            STSB(bufB ^ 1);
            if (c + 2 < nch) {
                LDGB(c + 2);
                asm volatile("cp.async.wait_group 1;" ::: "memory");
            } else {
                asm volatile("cp.async.wait_group 0;" ::: "memory");
            }
            __syncthreads();
        }
        if (++bufA == 3) bufA = 0;
    }
#undef CPA
#undef LDGB
#undef STSB
}

// z-sliced GEMM: per-slice A, B, C, K, lda
__global__ __launch_bounds__(256) void tf32gemm_kernel(
    const float* __restrict__ A0, const float* __restrict__ A1,
    const float* __restrict__ A2,
    const float* __restrict__ B0, const float* __restrict__ B1,
    const float* __restrict__ B2,
    void* __restrict__ C0, void* __restrict__ C1, void* __restrict__ C2,
    int bfmask, int Ndim, int4 Kdims, int4 Ldas)
{
    const float* Ap;
    const float* Bp;
    void* Cp;
    int kd, lda;
    switch (blockIdx.z) {
        case 0: Ap = A0; Bp = B0; Cp = C0; kd = Kdims.x; lda = Ldas.x; break;
        case 1: Ap = A1; Bp = B1; Cp = C1; kd = Kdims.y; lda = Ldas.y; break;
        default: Ap = A2; Bp = B2; Cp = C2; kd = Kdims.z; lda = Ldas.z; break;
    }
    const bool bf16out = (bfmask >> blockIdx.z) & 1;

    __shared__ __align__(16) char smem_raw[40960];
    const unsigned sbase = (unsigned)__cvta_generic_to_shared(smem_raw);

    const int tid = threadIdx.x;
    const int bm = blockIdx.y * 128, bn = blockIdx.x * 64;
    const int lane = tid & 31;
    const int w = tid >> 5;
    const int wm = w & 3, wn = w >> 2;
    const int lq = lane >> 2, lr = lane & 3;

    const unsigned a_l = sbase + (wm * 32 + (lane & 15)) * 80 + (lane >> 4) * 16;
    const unsigned b_l = sbase + 30720 +
        (wn * 32 + (lane & 7) + ((lane >> 4) & 1) * 8) * 80 + ((lane >> 3) & 1) * 16;

    float acc[2][4][4];
#pragma unroll
    for (int i = 0; i < 2; i++)
#pragma unroll
        for (int j = 0; j < 4; j++)
#pragma unroll
            for (int u = 0; u < 4; u++) acc[i][j][u] = 0.f;

    gemm_phase(Ap, Bp, kd, lda, Ndim, sbase, tid, bm, bn, a_l, b_l, acc);

#pragma unroll
    for (int i = 0; i < 2; i++) {
#pragma unroll
        for (int j = 0; j < 4; j++) {
            int row = bm + wm * 32 + i * 16 + lq;
            int col = bn + wn * 32 + j * 8 + lr * 2;
            if (bf16out) {
                __nv_bfloat16* Cb = (__nv_bfloat16*)Cp;
                *(__nv_bfloat162*)(Cb + (size_t)row * Ndim + col) =
                    __float22bfloat162_rn(make_float2(acc[i][j][0], acc[i][j][1]));
                *(__nv_bfloat162*)(Cb + (size_t)(row + 8) * Ndim + col) =
                    __float22bfloat162_rn(make_float2(acc[i][j][2], acc[i][j][3]));
            } else {
                float* Cf = (float*)Cp;
                *(float2*)(Cf + (size_t)row * Ndim + col) =
                    make_float2(acc[i][j][0], acc[i][j][1]);
                *(float2*)(Cf + (size_t)(row + 8) * Ndim + col) =
                    make_float2(acc[i][j][2], acc[i][j][3]);
            }
        }
    }
}

// final GEMM (N=64=AA) with fused rmsnorm epilogue: out = rmsnorm(x@Wact, lnf)
__global__ __launch_bounds__(256) void tf32gemm_final_kernel(
    const float* __restrict__ A, const float* __restrict__ B,
    const float* __restrict__ lnf, float* __restrict__ out)
{
    __shared__ __align__(16) char smem_raw[40960];
    __shared__ float s_ss[128][2];
    const unsigned sbase = (unsigned)__cvta_generic_to_shared(smem_raw);

    const int tid = threadIdx.x;
    const int bm = blockIdx.y * 128;
    const int lane = tid & 31;
    const int w = tid >> 5;
    const int wm = w & 3, wn = w >> 2;
    const int lq = lane >> 2, lr = lane & 3;

    const unsigned a_l = sbase + (wm * 32 + (lane & 15)) * 80 + (lane >> 4) * 16;
    const unsigned b_l = sbase + 30720 +
        (wn * 32 + (lane & 7) + ((lane >> 4) & 1) * 8) * 80 + ((lane >> 3) & 1) * 16;

    float acc[2][4][4];
#pragma unroll
    for (int i = 0; i < 2; i++)
#pragma unroll
        for (int j = 0; j < 4; j++)
#pragma unroll
            for (int u = 0; u < 4; u++) acc[i][j][u] = 0.f;

    gemm_phase(A, B, DD, DD, AA, sbase, tid, bm, 0, a_l, b_l, acc);

    // row sum-of-squares: reduce over j+lr within warp, over wn via smem
#pragma unroll
    for (int i = 0; i < 2; i++) {
        float s0 = 0.f, s1 = 0.f;
#pragma unroll
        for (int j = 0; j < 4; j++) {
            s0 += acc[i][j][0] * acc[i][j][0] + acc[i][j][1] * acc[i][j][1];
            s1 += acc[i][j][2] * acc[i][j][2] + acc[i][j][3] * acc[i][j][3];
        }
#pragma unroll
        for (int o = 1; o < 4; o <<= 1) {
            s0 += __shfl_xor_sync(0xffffffffu, s0, o);
            s1 += __shfl_xor_sync(0xffffffffu, s1, o);
        }
        if (lr == 0) {
            s_ss[wm * 32 + i * 16 + lq][wn] = s0;
            s_ss[wm * 32 + i * 16 + lq + 8][wn] = s1;
        }
    }
    __syncthreads();

#pragma unroll
    for (int i = 0; i < 2; i++) {
        int l0 = wm * 32 + i * 16 + lq, l1 = l0 + 8;
        float r0 = rsqrtf((s_ss[l0][0] + s_ss[l0][1]) / (float)AA + EPS);
        float r1 = rsqrtf((s_ss[l1][0] + s_ss[l1][1]) / (float)AA + EPS);
#pragma unroll
        for (int j = 0; j < 4; j++) {
            int col = wn * 32 + j * 8 + lr * 2;
            float w0 = lnf[col], w1 = lnf[col + 1];
            *(float2*)(out + (size_t)(bm + l0) * AA + col) =
                make_float2(acc[i][j][0] * r0 * w0, acc[i][j][1] * r0 * w1);
            *(float2*)(out + (size_t)(bm + l1) * AA + col) =
                make_float2(acc[i][j][2] * r1 * w0, acc[i][j][3] * r1 * w1);
        }
    }
}

// ---------------- attention: warp = edge-quarter, lanes cover all 4 heads ----------------
__device__ __forceinline__ float2 bf2f(unsigned u) {
    __nv_bfloat162 h = *reinterpret_cast<__nv_bfloat162*>(&u);
    return __bfloat1622float2(h);
}

__device__ __forceinline__ float dot16(const float* q, uint4 a, uint4 b) {
    float s = 0.f;
    const unsigned* wa = (const unsigned*)&a;
#pragma unroll
    for (int i = 0; i < 4; i++) {
        float2 f = bf2f(wa[i]);
        s += q[2 * i] * f.x + q[2 * i + 1] * f.y;
    }
    const unsigned* wb = (const unsigned*)&b;
#pragma unroll
    for (int i = 0; i < 4; i++) {
        float2 f = bf2f(wb[i]);
        s += q[8 + 2 * i] * f.x + q[9 + 2 * i] * f.y;
    }
    return s;
}

__device__ __forceinline__ void axpy16(float* acc, float fold, float w, uint4 a, uint4 b) {
    const unsigned* wa = (const unsigned*)&a;
#pragma unroll
    for (int i = 0; i < 4; i++) {
        float2 f = bf2f(wa[i]);
        acc[2 * i]     = acc[2 * i] * fold + w * f.x;
        acc[2 * i + 1] = acc[2 * i + 1] * fold + w * f.y;
    }
    const unsigned* wb = (const unsigned*)&b;
#pragma unroll
    for (int i = 0; i < 4; i++) {
        float2 f = bf2f(wb[i]);
        acc[8 + 2 * i] = acc[8 + 2 * i] * fold + w * f.x;
        acc[9 + 2 * i] = acc[9 + 2 * i] * fold + w * f.y;
    }
}

__global__ __launch_bounds__(128) void attn_kernel(int r) {
    const int j = blockIdx.x;
    const int tid = threadIdx.x;
    const int warp = tid >> 5, lane = tid & 31;
    const int h = lane >> 3, sub = lane & 7;
    const int hd0 = h * DD + sub * 16;
    const size_t jbase = (size_t)j * HO + hd0;

    float qr[16];
    {
        const float4* qp4 = (const float4*)(g_q + jbase);
#pragma unroll
        for (int i = 0; i < 4; i++) {
            float4 v = qp4[i];
            qr[i * 4 + 0] = v.x; qr[i * 4 + 1] = v.y;
            qr[i * 4 + 2] = v.z; qr[i * 4 + 3] = v.w;
        }
    }
    float qMx = 0.f, qMy = 0.f;
    {
        const float* mx = g_M[r] + hd0;
        const float* my = g_M[r] + HO + hd0;
#pragma unroll
        for (int i = 0; i < 16; i++) { qMx += qr[i] * mx[i]; qMy += qr[i] * my[i]; }
#pragma unroll
        for (int o = 1; o < 8; o <<= 1) {
            qMx += __shfl_xor_sync(0xffffffffu, qMx, o);
            qMy += __shfl_xor_sync(0xffffffffu, qMy, o);
        }
    }

    float m = -1e30f, den = 0.f, cx = 0.f, cy = 0.f;
    float acc[16];
#pragma unroll
    for (int i = 0; i < 16; i++) acc[i] = 0.f;

    if (warp == 0) {
        uint4 k0 = *(const uint4*)(g_kb + jbase);
        uint4 k1 = *(const uint4*)(g_kb + jbase + 8);
        uint4 v0 = *(const uint4*)(g_vb + jbase);
        uint4 v1 = *(const uint4*)(g_vb + jbase + 8);
        float part = dot16(qr, k0, k1);
#pragma unroll
        for (int o = 1; o < 8; o <<= 1) part += __shfl_xor_sync(0xffffffffu, part, o);
        m = part * SCALE;
        den = 1.f;
        axpy16(acc, 0.f, 1.f, v0, v1);
    }

    const int e0 = g_indptr[j], e1 = g_indptr[j + 1];
    for (int ei = e0 + warp; ei < e1; ei += 4) {
        int s = g_esrc[ei];
        float2 rr = g_erel[ei];
        const size_t sb = (size_t)s * HO + hd0;
        uint4 k0 = *(const uint4*)(g_kb + sb);
        uint4 k1 = *(const uint4*)(g_kb + sb + 8);
        uint4 v0 = *(const uint4*)(g_vb + sb);
        uint4 v1 = *(const uint4*)(g_vb + sb + 8);
        float part = dot16(qr, k0, k1) + (rr.x * qMx + rr.y * qMy) * 0.125f;
#pragma unroll
        for (int o = 1; o < 8; o <<= 1) part += __shfl_xor_sync(0xffffffffu, part, o);
        float alpha = part * SCALE;
        float mn = fmaxf(m, alpha);
        float fold = __expf(m - mn);
        float w = __expf(alpha - mn);
        den = den * fold + w;
        cx = cx * fold + w * rr.x;
        cy = cy * fold + w * rr.y;
        axpy16(acc, fold, w, v0, v1);
        m = mn;
    }

    __shared__ float s_m[4][4], s_den[4][4], s_cx[4][4], s_cy[4][4];
    __shared__ float s_acc[4][HO];
    if (sub == 0) {
        s_m[warp][h] = m; s_den[warp][h] = den;
        s_cx[warp][h] = cx; s_cy[warp][h] = cy;
    }
#pragma unroll
    for (int i = 0; i < 4; i++)
        *(float4*)&s_acc[warp][hd0 + i * 4] =
            make_float4(acc[i * 4], acc[i * 4 + 1], acc[i * 4 + 2], acc[i * 4 + 3]);
    __syncthreads();

    const int d = tid * 4;
    const int hh = tid >> 5;
    float M = fmaxf(fmaxf(s_m[0][hh], s_m[1][hh]), fmaxf(s_m[2][hh], s_m[3][hh]));
    float f0 = __expf(s_m[0][hh] - M), f1 = __expf(s_m[1][hh] - M);
    float f2 = __expf(s_m[2][hh] - M), f3 = __expf(s_m[3][hh] - M);
    float dtot = s_den[0][hh] * f0 + s_den[1][hh] * f1 + s_den[2][hh] * f2 + s_den[3][hh] * f3;
    float cxT = s_cx[0][hh] * f0 + s_cx[1][hh] * f1 + s_cx[2][hh] * f2 + s_cx[3][hh] * f3;
    float cyT = s_cy[0][hh] * f0 + s_cy[1][hh] * f1 + s_cy[2][hh] * f2 + s_cy[3][hh] * f3;
    float inv = 1.f / dtot;
    const float* mx = g_M[r] + d;
    const float* my = g_M[r] + HO + d;
    float o4[4];
#pragma unroll
    for (int i = 0; i < 4; i++) {
        float a = s_acc[0][d + i] * f0 + s_acc[1][d + i] * f1 +
                  s_acc[2][d + i] * f2 + s_acc[3][d + i] * f3;
        o4[i] = tf32r((a + cxT * mx[i] + cyT * my[i]) * inv);
    }
    *(float4*)(g_t + (size_t)j * HO + d) = make_float4(o4[0], o4[1], o4[2], o4[3]);
}

// x_out = tf32(rmsnorm(y1 + y2 + y3 + x_in, ln_w))
__global__ __launch_bounds__(128) void rmsres_kernel(const float* __restrict__ lnw) {
    int j = blockIdx.x, d = threadIdx.x;
    size_t i = (size_t)j * DD + d;
    float val = g_y1[i] + g_y2[i] + g_y3[i] + g_x[i];
    float ss = val * val;
#pragma unroll
    for (int off = 16; off; off >>= 1) ss += __shfl_xor_sync(0xffffffffu, ss, off);
    __shared__ float w4[4];
    if ((threadIdx.x & 31) == 0) w4[threadIdx.x >> 5] = ss;
    __syncthreads();
    float tot = w4[0] + w4[1] + w4[2] + w4[3];
    float r = rsqrtf(tot / (float)DD + EPS);
    g_x[i] = tf32r(val * r * lnw[d]);
}

// ---------------- launch ----------------
extern "C" void kernel_launch(void* const* d_in, const int* in_sizes, int n_in,
                              void* d_out, int out_size) {
    const float* node_features = (const float*)d_in[0];
    const int*   ids           = (const int*)d_in[1];
    const float* rel           = (const float*)d_in[2];
    const float* We_emb        = (const float*)d_in[3];
    const float* Wq            = (const float*)d_in[4];
    const float* Wk            = (const float*)d_in[5];
    const float* Wv            = (const float*)d_in[6];
    const float* Wedge         = (const float*)d_in[7];
    const float* Wskip         = (const float*)d_in[8];
    const float* Wout          = (const float*)d_in[9];
    const float* lnw           = (const float*)d_in[10];
    const float* Wact          = (const float*)d_in[11];
    const float* lnf           = (const float*)d_in[12];
    float* out = (float*)d_out;

    float *xp, *qp, *tp, *y1p, *y2p, *y3p, *wswp, *wqcp, *wkcp, *wvcp, *wocp, *wacp;
    __nv_bfloat16 *kbp, *vbp;
    cudaGetSymbolAddress((void**)&xp, g_x);
    cudaGetSymbolAddress((void**)&qp, g_q);
    cudaGetSymbolAddress((void**)&kbp, g_kb);
    cudaGetSymbolAddress((void**)&vbp, g_vb);
    cudaGetSymbolAddress((void**)&tp, g_t);
    cudaGetSymbolAddress((void**)&y1p, g_y1);
    cudaGetSymbolAddress((void**)&y2p, g_y2);
    cudaGetSymbolAddress((void**)&y3p, g_y3);
    cudaGetSymbolAddress((void**)&wswp, g_wsw);
    cudaGetSymbolAddress((void**)&wqcp, g_wqc);
    cudaGetSymbolAddress((void**)&wkcp, g_wkc);
    cudaGetSymbolAddress((void**)&wvcp, g_wvc);
    cudaGetSymbolAddress((void**)&wocp, g_woc);
    cudaGetSymbolAddress((void**)&wacp, g_wac);

    static cudaStream_t s1 = nullptr;
    static cudaEvent_t evFork = nullptr, evJoin = nullptr;
    static cudaEvent_t evX[RR], evY3[RR];
    if (!s1) {
        cudaStreamCreateWithFlags(&s1, cudaStreamNonBlocking);
        cudaEventCreateWithFlags(&evFork, cudaEventDisableTiming);
        cudaEventCreateWithFlags(&evJoin, cudaEventDisableTiming);
        for (int r = 0; r < RR; r++) {
            cudaEventCreateWithFlags(&evX[r], cudaEventDisableTiming);
            cudaEventCreateWithFlags(&evY3[r], cudaEventDisableTiming);
        }
    }

    dim3 gqkv(HO / 64, NN / 128, 3);
    dim3 gy12(DD / 64, NN / 128, 2);
    dim3 gy3(DD / 64, NN / 128, 1);
    dim3 gfin(1, NN / 128, 1);

    cudaEventRecord(evFork, 0);
    cudaStreamWaitEvent(s1, evFork, 0);

    // side stream: edge build + prep, then per-round y3 GEMMs
    zero_detect_kernel<<<(NN + 255) / 256, 256, 0, s1>>>(ids);
    count_kernel<<<(ENBR + 255) / 256, 256, 0, s1>>>(ids);
    scan_kernel<<<1, 1024, 0, s1>>>();
    scatter_kernel<<<(ENBR + 255) / 256, 256, 0, s1>>>(ids, rel);
    prep_kernel<<<dim3(DD + 4, RR), 128, 0, s1>>>(We_emb, Wedge, Wskip, Wout);
    cudaEventRecord(evJoin, s1);

    // main: conv + QKV r0
    conv_kernel<<<(NN * DD + 255) / 256, 256>>>(Wq, Wk, Wv, Wout, Wact, node_features);
    cudaEventRecord(evX[0], 0);
    tf32gemm_kernel<<<gqkv, 256>>>(xp, xp, xp, wqcp, wkcp, wvcp,
                                   qp, kbp, vbp, /*bfmask=*/0b110, HO,
                                   make_int4(DD, DD, DD, 0),
                                   make_int4(DD, DD, DD, 0));
    cudaStreamWaitEvent(0, evJoin, 0);   // edges + M ready before attention

    for (int r = 0; r < RR; r++) {
        if (r > 0) {
            const float* wq = wqcp + (size_t)r * DD * HO;
            const float* wk = wkcp + (size_t)r * DD * HO;
            const float* wv = wvcp + (size_t)r * DD * HO;
            tf32gemm_kernel<<<gqkv, 256>>>(xp, xp, xp, wq, wk, wv,
                                           qp, kbp, vbp, 0b110, HO,
                                           make_int4(DD, DD, DD, 0),
                                           make_int4(DD, DD, DD, 0));
        }
        // side stream: y3 = x @ Wsw concurrently with attention (+QKV tail)
        cudaStreamWaitEvent(s1, evX[r], 0);
        tf32gemm_kernel<<<gy3, 256, 0, s1>>>(xp, xp, xp,
                                             wswp + (size_t)r * DD * DD,
                                             wswp + (size_t)r * DD * DD,
                                             wswp + (size_t)r * DD * DD,
                                             y3p, y3p, y3p, /*bfmask=*/0, DD,
                                             make_int4(DD, DD, DD, 0),
                                             make_int4(DD, DD, DD, 0));
        cudaEventRecord(evY3[r], s1);

        attn_kernel<<<NN, 128>>>(r);
        // y1 = t[:,0:256]@Wout[0:256], y2 = t[:,256:512]@Wout[256:512]
        const float* wo = wocp + (size_t)r * HO * DD;
        tf32gemm_kernel<<<gy12, 256>>>(tp, tp + 256, tp,
                                       wo, wo + 256 * DD, wo,
                                       y1p, y2p, y1p, /*bfmask=*/0, DD,
                                       make_int4(256, 256, 256, 0),
                                       make_int4(HO, HO, HO, 0));
        cudaStreamWaitEvent(0, evY3[r], 0);
        rmsres_kernel<<<NN, DD>>>(lnw + (size_t)r * DD);
        if (r + 1 < RR) cudaEventRecord(evX[r + 1], 0);
    }

    // fused final GEMM + rmsnorm
    tf32gemm_final_kernel<<<gfin, 256>>>(xp, wacp, lnf, out);
}